// round 1
// baseline (speedup 1.0000x reference)
#include <cuda_runtime.h>
#include <cuda_bf16.h>
#include <math.h>

// ---------------- problem constants ----------------
#define MAXN   20000
#define INCH   64
#define HID    512
#define NPRED  12

// ---------------- scratch buffers (device globals; no runtime alloc) ----------------
__device__ float g_ax  [MAXN * INCH];       // aggregated input (layer0 trick)
__device__ float g_h   [MAXN * HID];        // current activations
__device__ float g_t   [MAXN * HID];        // pre-aggregation gemm output
__device__ float g_agg [MAXN * HID];        // aggregated hidden
__device__ float g_gates[MAXN * 4 * HID];   // LSTM gates
__device__ float g_c   [MAXN * HID];        // cell state
__device__ float g_ht  [MAXN * HID];        // hidden state
__device__ float g_peep[MAXN * 2 * HID];    // peephole gemm outputs
__device__ float g_bnsums[2 * HID];         // per-column sum / sumsq

// ---------------- utility kernels ----------------
__global__ void zero_kernel(float* __restrict__ p, long long n4) {
    long long i = (long long)blockIdx.x * blockDim.x + threadIdx.x;
    if (i < n4) reinterpret_cast<float4*>(p)[i] = make_float4(0.f, 0.f, 0.f, 0.f);
}

// edge aggregation: out[dst] += ew * feat[src], C columns, C/4 = 1<<shift groups
__global__ void agg_kernel(const float* __restrict__ feat,
                           const int* __restrict__ src,
                           const int* __restrict__ dst,
                           const float* __restrict__ ew,
                           float* __restrict__ out,
                           long long total, int shift, int C) {
    long long idx = (long long)blockIdx.x * blockDim.x + threadIdx.x;
    if (idx >= total) return;
    int e = (int)(idx >> shift);
    int g = ((int)idx & ((1 << shift) - 1)) << 2;
    float w = ew[e];
    int s = src[e], d = dst[e];
    float4 v = *reinterpret_cast<const float4*>(feat + (size_t)s * C + g);
    float* p = out + (size_t)d * C + g;
    atomicAdd(p + 0, v.x * w);
    atomicAdd(p + 1, v.y * w);
    atomicAdd(p + 2, v.z * w);
    atomicAdd(p + 3, v.w * w);
}

// per-column sum & sum-of-squares; block = 512 threads (one per column)
__global__ void bn_stats_kernel(const float* __restrict__ x, float* __restrict__ sums,
                                int Nrows, int C) {
    int col = threadIdx.x;
    int rowsPerBlock = (Nrows + gridDim.x - 1) / gridDim.x;
    int r0 = blockIdx.x * rowsPerBlock;
    int r1 = min(Nrows, r0 + rowsPerBlock);
    float s = 0.f, s2 = 0.f;
    for (int r = r0; r < r1; r++) {
        float v = x[(size_t)r * C + col];
        s += v;
        s2 = fmaf(v, v, s2);
    }
    atomicAdd(&sums[col], s);
    atomicAdd(&sums[C + col], s2);
}

__global__ void bn_apply_relu_kernel(const float* __restrict__ x, float* __restrict__ y,
                                     const float* __restrict__ sums,
                                     const float* __restrict__ gamma,
                                     const float* __restrict__ beta,
                                     long long total, float invN) {
    long long idx = (long long)blockIdx.x * blockDim.x + threadIdx.x;
    if (idx >= total) return;
    int col = (int)idx & (HID - 1);
    float mu  = sums[col] * invN;
    float var = sums[HID + col] * invN - mu * mu;
    float sc  = gamma[col] * rsqrtf(var + 1e-5f);
    float v   = (x[idx] - mu) * sc + beta[col];
    y[idx] = fmaxf(v, 0.f);
}

__device__ __forceinline__ float sigmoidf_(float x) { return 1.f / (1.f + expf(-x)); }

// layer0 cell part A: c = sigmoid(i) * tanh(g)   (h0 = c0 = 0)
__global__ void cell0a_kernel(const float* __restrict__ gates, float* __restrict__ c,
                              long long total) {
    long long idx = (long long)blockIdx.x * blockDim.x + threadIdx.x;
    if (idx >= total) return;
    long long row = idx >> 9;
    int col = (int)idx & (HID - 1);
    const float* g = gates + row * (4 * HID);
    c[idx] = sigmoidf_(g[col]) * tanhf(g[2 * HID + col]);
}

// shared by both layers: ht = sigmoid(o_gate + opeep) * tanh(c)
__global__ void cell_ob_kernel(const float* __restrict__ gates, const float* __restrict__ op,
                               const float* __restrict__ c, float* __restrict__ ht,
                               long long total) {
    long long idx = (long long)blockIdx.x * blockDim.x + threadIdx.x;
    if (idx >= total) return;
    long long row = idx >> 9;
    int col = (int)idx & (HID - 1);
    float o = gates[row * (4 * HID) + 3 * HID + col] + op[idx];
    ht[idx] = sigmoidf_(o) * tanhf(c[idx]);
}

// layer1 cell part A: i,f,g with peepholes; c <- f*c + i*g (in place)
__global__ void cell1a_kernel(const float* __restrict__ gates, const float* __restrict__ cp,
                              float* __restrict__ c, long long total) {
    long long idx = (long long)blockIdx.x * blockDim.x + threadIdx.x;
    if (idx >= total) return;
    long long row = idx >> 9;
    int col = (int)idx & (HID - 1);
    const float* g = gates + row * (4 * HID);
    const float* p = cp + row * (2 * HID);
    float ig = sigmoidf_(g[col]);
    float fg = sigmoidf_(g[HID + col] + p[HID + col]);
    float gg = tanhf(g[2 * HID + col] + p[col]);
    c[idx] = fg * c[idx] + ig * gg;
}

// ---------------- SGEMM: C[M,Nc] = A[M,K] @ B[K,Nc] (+bias / +=) ----------------
#define GBM 128
#define GBN 128
#define GBK 16
#define GTM 8
#define GTN 8

template <bool BIAS, bool ACCUM>
__global__ __launch_bounds__(256)
void sgemm_kernel(const float* __restrict__ A, const float* __restrict__ B,
                  float* __restrict__ C, const float* __restrict__ bias,
                  int M, int Ncols, int K, int lda, int ldb, int ldc) {
    __shared__ float As[GBK][GBM];
    __shared__ float Bs[GBK][GBN];

    int tid = threadIdx.x;
    int bm = blockIdx.y * GBM;
    int bn = blockIdx.x * GBN;
    int ty = tid >> 4;   // 0..15
    int tx = tid & 15;   // 0..15

    float acc[GTM][GTN];
#pragma unroll
    for (int i = 0; i < GTM; i++)
#pragma unroll
        for (int j = 0; j < GTN; j++) acc[i][j] = 0.f;

    for (int k0 = 0; k0 < K; k0 += GBK) {
        // load A tile: 128 rows x 16 cols = 512 float4
#pragma unroll
        for (int it = 0; it < 2; it++) {
            int l = tid + it * 256;
            int r  = l >> 2;
            int c4 = (l & 3) << 2;
            float4 v = make_float4(0.f, 0.f, 0.f, 0.f);
            int row = bm + r;
            if (row < M)
                v = *reinterpret_cast<const float4*>(A + (size_t)row * lda + k0 + c4);
            As[c4 + 0][r] = v.x;
            As[c4 + 1][r] = v.y;
            As[c4 + 2][r] = v.z;
            As[c4 + 3][r] = v.w;
        }
        // load B tile: 16 rows x 128 cols = 512 float4
#pragma unroll
        for (int it = 0; it < 2; it++) {
            int l = tid + it * 256;
            int r  = l >> 5;
            int c4 = (l & 31) << 2;
            int col = bn + c4;
            const float* bp = B + (size_t)(k0 + r) * ldb;
            float4 v = make_float4(0.f, 0.f, 0.f, 0.f);
            if (col + 3 < Ncols) {
                v = *reinterpret_cast<const float4*>(bp + col);
            } else {
                if (col + 0 < Ncols) v.x = bp[col + 0];
                if (col + 1 < Ncols) v.y = bp[col + 1];
                if (col + 2 < Ncols) v.z = bp[col + 2];
                if (col + 3 < Ncols) v.w = bp[col + 3];
            }
            *reinterpret_cast<float4*>(&Bs[r][c4]) = v;
        }
        __syncthreads();

#pragma unroll
        for (int k = 0; k < GBK; k++) {
            float4 a0 = *reinterpret_cast<const float4*>(&As[k][ty * GTM]);
            float4 a1 = *reinterpret_cast<const float4*>(&As[k][ty * GTM + 4]);
            float4 b0 = *reinterpret_cast<const float4*>(&Bs[k][tx * GTN]);
            float4 b1 = *reinterpret_cast<const float4*>(&Bs[k][tx * GTN + 4]);
            float a[GTM] = {a0.x, a0.y, a0.z, a0.w, a1.x, a1.y, a1.z, a1.w};
            float b[GTN] = {b0.x, b0.y, b0.z, b0.w, b1.x, b1.y, b1.z, b1.w};
#pragma unroll
            for (int i = 0; i < GTM; i++)
#pragma unroll
                for (int j = 0; j < GTN; j++)
                    acc[i][j] = fmaf(a[i], b[j], acc[i][j]);
        }
        __syncthreads();
    }

    // epilogue
#pragma unroll
    for (int i = 0; i < GTM; i++) {
        int row = bm + ty * GTM + i;
        if (row >= M) continue;
#pragma unroll
        for (int j = 0; j < GTN; j += 4) {
            int col = bn + tx * GTN + j;
            float* p = C + (size_t)row * ldc + col;
            if (col + 3 < Ncols) {
                float4 v = make_float4(acc[i][j], acc[i][j + 1], acc[i][j + 2], acc[i][j + 3]);
                if (BIAS) {
                    v.x += bias[col + 0]; v.y += bias[col + 1];
                    v.z += bias[col + 2]; v.w += bias[col + 3];
                }
                if (ACCUM) {
                    float4 o = *reinterpret_cast<const float4*>(p);
                    v.x += o.x; v.y += o.y; v.z += o.z; v.w += o.w;
                }
                *reinterpret_cast<float4*>(p) = v;
            } else {
                for (int jj = 0; jj < 4; jj++) {
                    int cc = col + jj;
                    if (cc < Ncols) {
                        float v = acc[i][j + jj];
                        if (BIAS)  v += bias[cc];
                        if (ACCUM) v += p[jj];
                        p[jj] = v;
                    }
                }
            }
        }
    }
}

// ---------------- host orchestration ----------------
static inline void run_gemm(const float* A, const float* B, float* C, const float* bias,
                            int M, int Nc, int K, int lda, int ldb, int ldc,
                            bool use_bias, bool accum) {
    dim3 grid((Nc + GBN - 1) / GBN, (M + GBM - 1) / GBM);
    if (use_bias)
        sgemm_kernel<true, false><<<grid, 256>>>(A, B, C, bias, M, Nc, K, lda, ldb, ldc);
    else if (accum)
        sgemm_kernel<false, true><<<grid, 256>>>(A, B, C, bias, M, Nc, K, lda, ldb, ldc);
    else
        sgemm_kernel<false, false><<<grid, 256>>>(A, B, C, bias, M, Nc, K, lda, ldb, ldc);
}

static inline void run_zero(float* p, long long nfloats) {
    long long n4 = nfloats >> 2;
    int blocks = (int)((n4 + 255) / 256);
    zero_kernel<<<blocks, 256>>>(p, n4);
}

extern "C" void kernel_launch(void* const* d_in, const int* in_sizes, int n_in,
                              void* d_out, int out_size) {
    const float* x        = (const float*)d_in[0];
    const int*   ei       = (const int*)  d_in[1];   // [2,E]
    const float* ew       = (const float*)d_in[2];   // [E]
    const float* gcn0_W   = (const float*)d_in[3];   // [64,512]
    // d_in[4] gcn0_b: cancels under BN (and is zero) -> unused
    const float* gcn_W    = (const float*)d_in[5];   // [2,512,512]
    // d_in[6] gcn_b: cancels under BN -> unused
    const float* bn_gamma = (const float*)d_in[7];   // [3,512]
    const float* bn_beta  = (const float*)d_in[8];   // [3,512]
    const float* w_ih     = (const float*)d_in[9];   // [2,512,2048]
    const float* w_hh     = (const float*)d_in[10];  // [2,512,2048]
    const float* w_ch     = (const float*)d_in[11];  // [2,512,1536]
    const float* lstm_b   = (const float*)d_in[12];  // [2,2048]
    const float* out_W    = (const float*)d_in[13];  // [512,12]
    const float* out_b    = (const float*)d_in[14];  // [12]
    float* out = (float*)d_out;

    const int N = in_sizes[0] / INCH;
    const int E = in_sizes[2];
    const int* src = ei;
    const int* dst = ei + E;
    const float invN = 1.f / (float)N;

    float *p_ax, *p_h, *p_t, *p_agg, *p_gates, *p_c, *p_ht, *p_peep, *p_sums;
    cudaGetSymbolAddress((void**)&p_ax,    g_ax);
    cudaGetSymbolAddress((void**)&p_h,     g_h);
    cudaGetSymbolAddress((void**)&p_t,     g_t);
    cudaGetSymbolAddress((void**)&p_agg,   g_agg);
    cudaGetSymbolAddress((void**)&p_gates, g_gates);
    cudaGetSymbolAddress((void**)&p_c,     g_c);
    cudaGetSymbolAddress((void**)&p_ht,    g_ht);
    cudaGetSymbolAddress((void**)&p_peep,  g_peep);
    cudaGetSymbolAddress((void**)&p_sums,  g_bnsums);

    const long long totNH = (long long)N * HID;
    const int blkNH = (int)((totNH + 255) / 256);
    const int bnStatBlocks = 160;

    // ---- GCN layer 0: aggregate input first (linearity), then matmul ----
    run_zero(p_ax, (long long)N * INCH);
    {
        long long total = (long long)E * (INCH / 4);
        agg_kernel<<<(int)((total + 255) / 256), 256>>>(x, src, dst, ew, p_ax, total, 4, INCH);
    }
    run_gemm(p_ax, gcn0_W, p_t, nullptr, N, HID, INCH, INCH, HID, HID, false, false);
    run_zero(p_sums, 2 * HID);
    bn_stats_kernel<<<bnStatBlocks, HID>>>(p_t, p_sums, N, HID);
    bn_apply_relu_kernel<<<blkNH, 256>>>(p_t, p_h, p_sums, bn_gamma, bn_beta, totNH, invN);

    // ---- GCN layers 1..2 ----
    for (int l = 0; l < 2; l++) {
        run_gemm(p_h, gcn_W + (size_t)l * HID * HID, p_t, nullptr,
                 N, HID, HID, HID, HID, HID, false, false);
        run_zero(p_agg, totNH);
        long long total = (long long)E * (HID / 4);
        agg_kernel<<<(int)((total + 255) / 256), 256>>>(p_t, src, dst, ew, p_agg, total, 7, HID);
        run_zero(p_sums, 2 * HID);
        bn_stats_kernel<<<bnStatBlocks, HID>>>(p_agg, p_sums, N, HID);
        bn_apply_relu_kernel<<<blkNH, 256>>>(p_agg, p_h, p_sums,
                                             bn_gamma + (l + 1) * HID, bn_beta + (l + 1) * HID,
                                             totNH, invN);
    }

    // ---- LSTM layer 0 (h0 = c0 = 0: skip Whh and i/f peepholes) ----
    run_gemm(p_h, w_ih, p_gates, lstm_b, N, 4 * HID, HID, HID, 4 * HID, 4 * HID, true, false);
    cell0a_kernel<<<blkNH, 256>>>(p_gates, p_c, totNH);
    run_gemm(p_c, w_ch + 2 * HID, p_peep, nullptr, N, HID, HID, HID, 3 * HID, HID, false, false);
    cell_ob_kernel<<<blkNH, 256>>>(p_gates, p_peep, p_c, p_ht, totNH);

    // ---- LSTM layer 1 (full) ----
    const float* wih1 = w_ih + (size_t)HID * 4 * HID;
    const float* whh1 = w_hh + (size_t)HID * 4 * HID;
    const float* wch1 = w_ch + (size_t)HID * 3 * HID;
    run_gemm(p_h,  wih1, p_gates, lstm_b + 4 * HID, N, 4 * HID, HID, HID, 4 * HID, 4 * HID, true,  false);
    run_gemm(p_ht, whh1, p_gates, nullptr,          N, 4 * HID, HID, HID, 4 * HID, 4 * HID, false, true);
    // g & f peepholes together: cp = c @ Wch1[:, 0:1024]
    run_gemm(p_c, wch1, p_peep, nullptr, N, 2 * HID, HID, HID, 3 * HID, 2 * HID, false, false);
    cell1a_kernel<<<blkNH, 256>>>(p_gates, p_peep, p_c, totNH);
    run_gemm(p_c, wch1 + 2 * HID, p_peep, nullptr, N, HID, HID, HID, 3 * HID, HID, false, false);
    cell_ob_kernel<<<blkNH, 256>>>(p_gates, p_peep, p_c, p_ht, totNH);

    // ---- output projection ----
    run_gemm(p_ht, out_W, out, out_b, N, NPRED, HID, HID, NPRED, NPRED, true, false);
}

// round 2
// speedup vs baseline: 1.5413x; 1.5413x over previous
#include <cuda_runtime.h>
#include <cuda_bf16.h>
#include <math.h>

// ---------------- problem constants ----------------
#define MAXN   20000
#define INCH   64
#define HID    512
#define NPRED  12

// ---------------- scratch buffers (device globals; no runtime alloc) ----------------
__device__ float g_ax  [MAXN * INCH];       // aggregated input (layer0 trick)
__device__ float g_h   [MAXN * HID];        // current activations
__device__ float g_t   [MAXN * HID];        // pre-aggregation gemm output
__device__ float g_agg [MAXN * HID];        // aggregated hidden
__device__ float g_gates[MAXN * 4 * HID];   // LSTM gates
__device__ float g_c   [MAXN * HID];        // cell state
__device__ float g_ht  [MAXN * HID];        // hidden state
__device__ float g_peep[MAXN * 2 * HID];    // peephole gemm outputs
__device__ float g_bnsums[2 * HID];         // per-column sum / sumsq

// ---------------- utility kernels ----------------
__global__ void zero_kernel(float* __restrict__ p, long long n4) {
    long long i = (long long)blockIdx.x * blockDim.x + threadIdx.x;
    if (i < n4) reinterpret_cast<float4*>(p)[i] = make_float4(0.f, 0.f, 0.f, 0.f);
}

// edge aggregation: out[dst] += ew * feat[src], C columns, C/4 = 1<<shift groups
__global__ void agg_kernel(const float* __restrict__ feat,
                           const int* __restrict__ src,
                           const int* __restrict__ dst,
                           const float* __restrict__ ew,
                           float* __restrict__ out,
                           long long total, int shift, int C) {
    long long idx = (long long)blockIdx.x * blockDim.x + threadIdx.x;
    if (idx >= total) return;
    int e = (int)(idx >> shift);
    int g = ((int)idx & ((1 << shift) - 1)) << 2;
    float w = ew[e];
    int s = src[e], d = dst[e];
    float4 v = *reinterpret_cast<const float4*>(feat + (size_t)s * C + g);
    float* p = out + (size_t)d * C + g;
    atomicAdd(p + 0, v.x * w);
    atomicAdd(p + 1, v.y * w);
    atomicAdd(p + 2, v.z * w);
    atomicAdd(p + 3, v.w * w);
}

// per-column sum & sum-of-squares; block = 512 threads (one per column)
__global__ void bn_stats_kernel(const float* __restrict__ x, float* __restrict__ sums,
                                int Nrows, int C) {
    int col = threadIdx.x;
    int rowsPerBlock = (Nrows + gridDim.x - 1) / gridDim.x;
    int r0 = blockIdx.x * rowsPerBlock;
    int r1 = min(Nrows, r0 + rowsPerBlock);
    float s = 0.f, s2 = 0.f;
    for (int r = r0; r < r1; r++) {
        float v = x[(size_t)r * C + col];
        s += v;
        s2 = fmaf(v, v, s2);
    }
    atomicAdd(&sums[col], s);
    atomicAdd(&sums[C + col], s2);
}

__global__ void bn_apply_relu_kernel(const float* __restrict__ x, float* __restrict__ y,
                                     const float* __restrict__ sums,
                                     const float* __restrict__ gamma,
                                     const float* __restrict__ beta,
                                     long long total, float invN) {
    long long idx = (long long)blockIdx.x * blockDim.x + threadIdx.x;
    if (idx >= total) return;
    int col = (int)idx & (HID - 1);
    float mu  = sums[col] * invN;
    float var = sums[HID + col] * invN - mu * mu;
    float sc  = gamma[col] * rsqrtf(var + 1e-5f);
    float v   = (x[idx] - mu) * sc + beta[col];
    y[idx] = fmaxf(v, 0.f);
}

__device__ __forceinline__ float sigmoidf_(float x) { return 1.f / (1.f + expf(-x)); }

// layer0 cell part A: c = sigmoid(i) * tanh(g)   (h0 = c0 = 0)
__global__ void cell0a_kernel(const float* __restrict__ gates, float* __restrict__ c,
                              long long total) {
    long long idx = (long long)blockIdx.x * blockDim.x + threadIdx.x;
    if (idx >= total) return;
    long long row = idx >> 9;
    int col = (int)idx & (HID - 1);
    const float* g = gates + row * (4 * HID);
    c[idx] = sigmoidf_(g[col]) * tanhf(g[2 * HID + col]);
}

// shared by both layers: ht = sigmoid(o_gate + opeep) * tanh(c)
__global__ void cell_ob_kernel(const float* __restrict__ gates, const float* __restrict__ op,
                               const float* __restrict__ c, float* __restrict__ ht,
                               long long total) {
    long long idx = (long long)blockIdx.x * blockDim.x + threadIdx.x;
    if (idx >= total) return;
    long long row = idx >> 9;
    int col = (int)idx & (HID - 1);
    float o = gates[row * (4 * HID) + 3 * HID + col] + op[idx];
    ht[idx] = sigmoidf_(o) * tanhf(c[idx]);
}

// layer1 cell part A: i,f,g with peepholes; c <- f*c + i*g (in place)
__global__ void cell1a_kernel(const float* __restrict__ gates, const float* __restrict__ cp,
                              float* __restrict__ c, long long total) {
    long long idx = (long long)blockIdx.x * blockDim.x + threadIdx.x;
    if (idx >= total) return;
    long long row = idx >> 9;
    int col = (int)idx & (HID - 1);
    const float* g = gates + row * (4 * HID);
    const float* p = cp + row * (2 * HID);
    float ig = sigmoidf_(g[col]);
    float fg = sigmoidf_(g[HID + col] + p[HID + col]);
    float gg = tanhf(g[2 * HID + col] + p[col]);
    c[idx] = fg * c[idx] + ig * gg;
}

// ---------------- TF32 tensor-core GEMM ----------------
// C[M,Nc] = A[M,K] @ B[K,Nc], 128x128x32 block tile, 8 warps, 64x32 warp tile,
// mma.sync.m16n8k8.tf32. Fragment-native smem layout: each (frag, lane) is a
// contiguous uint4 (A) / uint2 (B) -> conflict-free LDS/STS.

__device__ __forceinline__ unsigned f2t(float x) {
    unsigned r;
    asm("cvt.rna.tf32.f32 %0, %1;" : "=r"(r) : "f"(x));
    return r;
}

template <int MODE>   // 0 = plain, 1 = +bias, 2 = += C
__global__ __launch_bounds__(256)
void tgemm_kernel(const float* __restrict__ A, const float* __restrict__ B,
                  float* __restrict__ C, const float* __restrict__ bias,
                  int M, int Ncols, int K, int lda, int ldb, int ldc) {
    // A: 32 fragments (8 m-tiles x 4 k-tiles), 128 words each
    // B: 64 fragments (16 n-tiles x 4 k-tiles), 64 words each
    __shared__ unsigned As[32 * 128];
    __shared__ unsigned Bs[64 * 64];

    const int tid  = threadIdx.x;
    const int lane = tid & 31;
    const int warp = tid >> 5;
    const int bm = blockIdx.y * 128;
    const int bn = blockIdx.x * 128;
    const int wm = (warp >> 2) * 64;   // 0 or 64
    const int wn = (warp & 3) * 32;    // 0,32,64,96

    float acc[4][4][4];
#pragma unroll
    for (int i = 0; i < 4; i++)
#pragma unroll
        for (int j = 0; j < 4; j++)
#pragma unroll
            for (int k = 0; k < 4; k++) acc[i][j][k] = 0.f;

    float pa[4][4];   // prefetch A (4 frag-lane pairs x 4 regs)
    float pb[8][2];   // prefetch B (8 frag-lane pairs x 2 regs)

    const int T = K >> 5;

    // ---- global loads for tile at k0 (into registers) ----
    auto loadA = [&](int k0) {
#pragma unroll
        for (int it = 0; it < 4; it++) {
            int p  = tid + it * 256;
            int fi = p >> 5, ln = p & 31;
            int mt = fi >> 2, kt = fi & 3;
            int m  = bm + mt * 16 + (ln >> 2);
            int k  = k0 + kt * 8 + (ln & 3);
            const float* a0 = A + (size_t)m * lda + k;
            bool ok0 = (m < M), ok1 = (m + 8 < M);
            pa[it][0] = ok0 ? a0[0] : 0.f;
            pa[it][1] = ok1 ? a0[(size_t)8 * lda] : 0.f;
            pa[it][2] = ok0 ? a0[4] : 0.f;
            pa[it][3] = ok1 ? a0[(size_t)8 * lda + 4] : 0.f;
        }
    };
    auto loadB = [&](int k0) {
#pragma unroll
        for (int it = 0; it < 8; it++) {
            int p  = tid + it * 256;
            int fi = p >> 5, ln = p & 31;
            int nt = fi >> 2, kt = fi & 3;
            int k  = k0 + kt * 8 + (ln & 3);
            int n  = bn + nt * 8 + (ln >> 2);
            const float* b0 = B + (size_t)k * ldb + n;
            pb[it][0] = b0[0];
            pb[it][1] = b0[(size_t)4 * ldb];
        }
    };
    auto store = [&]() {
#pragma unroll
        for (int it = 0; it < 4; it++) {
            int p  = tid + it * 256;
            int fi = p >> 5, ln = p & 31;
            uint4 v = make_uint4(f2t(pa[it][0]), f2t(pa[it][1]), f2t(pa[it][2]), f2t(pa[it][3]));
            *reinterpret_cast<uint4*>(&As[fi * 128 + ln * 4]) = v;
        }
#pragma unroll
        for (int it = 0; it < 8; it++) {
            int p  = tid + it * 256;
            int fi = p >> 5, ln = p & 31;
            uint2 v = make_uint2(f2t(pb[it][0]), f2t(pb[it][1]));
            *reinterpret_cast<uint2*>(&Bs[fi * 64 + ln * 2]) = v;
        }
    };
    auto compute = [&]() {
#pragma unroll
        for (int kt = 0; kt < 4; kt++) {
            unsigned af[4][4];
#pragma unroll
            for (int mi = 0; mi < 4; mi++) {
                int fi = ((wm >> 4) + mi) * 4 + kt;
                uint4 v = *reinterpret_cast<const uint4*>(&As[fi * 128 + lane * 4]);
                af[mi][0] = v.x; af[mi][1] = v.y; af[mi][2] = v.z; af[mi][3] = v.w;
            }
            unsigned bf[4][2];
#pragma unroll
            for (int ni = 0; ni < 4; ni++) {
                int fi = ((wn >> 3) + ni) * 4 + kt;
                uint2 v = *reinterpret_cast<const uint2*>(&Bs[fi * 64 + lane * 2]);
                bf[ni][0] = v.x; bf[ni][1] = v.y;
            }
#pragma unroll
            for (int mi = 0; mi < 4; mi++)
#pragma unroll
                for (int ni = 0; ni < 4; ni++) {
                    asm volatile(
                        "mma.sync.aligned.m16n8k8.row.col.f32.tf32.tf32.f32 "
                        "{%0,%1,%2,%3}, {%4,%5,%6,%7}, {%8,%9}, {%0,%1,%2,%3};\n"
                        : "+f"(acc[mi][ni][0]), "+f"(acc[mi][ni][1]),
                          "+f"(acc[mi][ni][2]), "+f"(acc[mi][ni][3])
                        : "r"(af[mi][0]), "r"(af[mi][1]), "r"(af[mi][2]), "r"(af[mi][3]),
                          "r"(bf[ni][0]), "r"(bf[ni][1]));
                }
        }
    };

    loadA(0); loadB(0);
    store();
    __syncthreads();
    for (int t = 0; t < T; t++) {
        if (t + 1 < T) { loadA((t + 1) << 5); loadB((t + 1) << 5); }
        compute();
        __syncthreads();
        if (t + 1 < T) { store(); __syncthreads(); }
    }

    // ---- epilogue ----
    const int gq = lane >> 2;
    const int rr = (lane & 3) << 1;
#pragma unroll
    for (int mi = 0; mi < 4; mi++) {
#pragma unroll
        for (int ni = 0; ni < 4; ni++) {
            int col = bn + wn + ni * 8 + rr;
#pragma unroll
            for (int h = 0; h < 2; h++) {
                int r = bm + wm + mi * 16 + gq + h * 8;
                if (r < M) {
                    float2 v = make_float2(acc[mi][ni][h * 2], acc[mi][ni][h * 2 + 1]);
                    if (MODE == 1) { v.x += bias[col]; v.y += bias[col + 1]; }
                    float* p = C + (size_t)r * ldc + col;
                    if (MODE == 2) {
                        float2 o = *reinterpret_cast<const float2*>(p);
                        v.x += o.x; v.y += o.y;
                    }
                    *reinterpret_cast<float2*>(p) = v;
                }
            }
        }
    }
}

// ---------------- small fp32 GEMM for the 12-wide output projection ----------------
__global__ __launch_bounds__(256)
void outproj_kernel(const float* __restrict__ A, const float* __restrict__ B,
                    float* __restrict__ C, const float* __restrict__ bias,
                    int M, int Ncols, int K) {
    // one thread per (row, col): 20000 x 12
    long long idx = (long long)blockIdx.x * blockDim.x + threadIdx.x;
    long long total = (long long)M * Ncols;
    if (idx >= total) return;
    int row = (int)(idx / Ncols);
    int col = (int)(idx % Ncols);
    const float* a = A + (size_t)row * K;
    float s = bias[col];
    for (int k = 0; k < K; k += 4) {
        float4 v = *reinterpret_cast<const float4*>(a + k);
        s = fmaf(v.x, B[(size_t)(k + 0) * Ncols + col], s);
        s = fmaf(v.y, B[(size_t)(k + 1) * Ncols + col], s);
        s = fmaf(v.z, B[(size_t)(k + 2) * Ncols + col], s);
        s = fmaf(v.w, B[(size_t)(k + 3) * Ncols + col], s);
    }
    C[idx] = s;
}

// ---------------- host orchestration ----------------
static inline void run_tgemm(const float* A, const float* B, float* C, const float* bias,
                             int M, int Nc, int K, int lda, int ldb, int ldc, int mode) {
    dim3 grid(Nc / 128, (M + 127) / 128);
    if (mode == 1)
        tgemm_kernel<1><<<grid, 256>>>(A, B, C, bias, M, Nc, K, lda, ldb, ldc);
    else if (mode == 2)
        tgemm_kernel<2><<<grid, 256>>>(A, B, C, bias, M, Nc, K, lda, ldb, ldc);
    else
        tgemm_kernel<0><<<grid, 256>>>(A, B, C, bias, M, Nc, K, lda, ldb, ldc);
}

static inline void run_zero(float* p, long long nfloats) {
    long long n4 = nfloats >> 2;
    int blocks = (int)((n4 + 255) / 256);
    zero_kernel<<<blocks, 256>>>(p, n4);
}

extern "C" void kernel_launch(void* const* d_in, const int* in_sizes, int n_in,
                              void* d_out, int out_size) {
    const float* x        = (const float*)d_in[0];
    const int*   ei       = (const int*)  d_in[1];   // [2,E]
    const float* ew       = (const float*)d_in[2];   // [E]
    const float* gcn0_W   = (const float*)d_in[3];   // [64,512]
    // d_in[4] gcn0_b: cancels under BN -> unused
    const float* gcn_W    = (const float*)d_in[5];   // [2,512,512]
    // d_in[6] gcn_b: cancels under BN -> unused
    const float* bn_gamma = (const float*)d_in[7];   // [3,512]
    const float* bn_beta  = (const float*)d_in[8];   // [3,512]
    const float* w_ih     = (const float*)d_in[9];   // [2,512,2048]
    const float* w_hh     = (const float*)d_in[10];  // [2,512,2048]
    const float* w_ch     = (const float*)d_in[11];  // [2,512,1536]
    const float* lstm_b   = (const float*)d_in[12];  // [2,2048]
    const float* out_W    = (const float*)d_in[13];  // [512,12]
    const float* out_b    = (const float*)d_in[14];  // [12]
    float* out = (float*)d_out;

    const int N = in_sizes[0] / INCH;
    const int E = in_sizes[2];
    const int* src = ei;
    const int* dst = ei + E;
    const float invN = 1.f / (float)N;

    float *p_ax, *p_h, *p_t, *p_agg, *p_gates, *p_c, *p_ht, *p_peep, *p_sums;
    cudaGetSymbolAddress((void**)&p_ax,    g_ax);
    cudaGetSymbolAddress((void**)&p_h,     g_h);
    cudaGetSymbolAddress((void**)&p_t,     g_t);
    cudaGetSymbolAddress((void**)&p_agg,   g_agg);
    cudaGetSymbolAddress((void**)&p_gates, g_gates);
    cudaGetSymbolAddress((void**)&p_c,     g_c);
    cudaGetSymbolAddress((void**)&p_ht,    g_ht);
    cudaGetSymbolAddress((void**)&p_peep,  g_peep);
    cudaGetSymbolAddress((void**)&p_sums,  g_bnsums);

    const long long totNH = (long long)N * HID;
    const int blkNH = (int)((totNH + 255) / 256);
    const int bnStatBlocks = 160;

    // ---- GCN layer 0: aggregate input first (linearity), then matmul ----
    run_zero(p_ax, (long long)N * INCH);
    {
        long long total = (long long)E * (INCH / 4);
        agg_kernel<<<(int)((total + 255) / 256), 256>>>(x, src, dst, ew, p_ax, total, 4, INCH);
    }
    run_tgemm(p_ax, gcn0_W, p_t, nullptr, N, HID, INCH, INCH, HID, HID, 0);
    run_zero(p_sums, 2 * HID);
    bn_stats_kernel<<<bnStatBlocks, HID>>>(p_t, p_sums, N, HID);
    bn_apply_relu_kernel<<<blkNH, 256>>>(p_t, p_h, p_sums, bn_gamma, bn_beta, totNH, invN);

    // ---- GCN layers 1..2 ----
    for (int l = 0; l < 2; l++) {
        run_tgemm(p_h, gcn_W + (size_t)l * HID * HID, p_t, nullptr,
                  N, HID, HID, HID, HID, HID, 0);
        run_zero(p_agg, totNH);
        long long total = (long long)E * (HID / 4);
        agg_kernel<<<(int)((total + 255) / 256), 256>>>(p_t, src, dst, ew, p_agg, total, 7, HID);
        run_zero(p_sums, 2 * HID);
        bn_stats_kernel<<<bnStatBlocks, HID>>>(p_agg, p_sums, N, HID);
        bn_apply_relu_kernel<<<blkNH, 256>>>(p_agg, p_h, p_sums,
                                             bn_gamma + (l + 1) * HID, bn_beta + (l + 1) * HID,
                                             totNH, invN);
    }

    // ---- LSTM layer 0 (h0 = c0 = 0: skip Whh and i/f peepholes) ----
    run_tgemm(p_h, w_ih, p_gates, lstm_b, N, 4 * HID, HID, HID, 4 * HID, 4 * HID, 1);
    cell0a_kernel<<<blkNH, 256>>>(p_gates, p_c, totNH);
    run_tgemm(p_c, w_ch + 2 * HID, p_peep, nullptr, N, HID, HID, HID, 3 * HID, HID, 0);
    cell_ob_kernel<<<blkNH, 256>>>(p_gates, p_peep, p_c, p_ht, totNH);

    // ---- LSTM layer 1 (full) ----
    const float* wih1 = w_ih + (size_t)HID * 4 * HID;
    const float* whh1 = w_hh + (size_t)HID * 4 * HID;
    const float* wch1 = w_ch + (size_t)HID * 3 * HID;
    run_tgemm(p_h,  wih1, p_gates, lstm_b + 4 * HID, N, 4 * HID, HID, HID, 4 * HID, 4 * HID, 1);
    run_tgemm(p_ht, whh1, p_gates, nullptr,          N, 4 * HID, HID, HID, 4 * HID, 4 * HID, 2);
    // g & f peepholes together: cp = c @ Wch1[:, 0:1024]
    run_tgemm(p_c, wch1, p_peep, nullptr, N, 2 * HID, HID, HID, 3 * HID, 2 * HID, 0);
    cell1a_kernel<<<blkNH, 256>>>(p_gates, p_peep, p_c, totNH);
    run_tgemm(p_c, wch1 + 2 * HID, p_peep, nullptr, N, HID, HID, HID, 3 * HID, HID, 0);
    cell_ob_kernel<<<blkNH, 256>>>(p_gates, p_peep, p_c, p_ht, totNH);

    // ---- output projection (12-wide; FFMA path) ----
    {
        long long total = (long long)N * NPRED;
        outproj_kernel<<<(int)((total + 255) / 256), 256>>>(p_ht, out_W, out, out_b,
                                                            N, NPRED, HID);
    }
}

// round 4
// speedup vs baseline: 2.2976x; 1.4907x over previous
#include <cuda_runtime.h>
#include <cuda_fp16.h>
#include <math.h>
#include <stdint.h>

// ---------------- problem constants ----------------
#define MAXN   20000
#define INCH   64
#define HID    512
#define NPRED  12

// ---------------- scratch buffers (device globals; no runtime alloc) ----------------
__device__ __align__(256) float g_ax  [MAXN * INCH];
__device__ __align__(256) float g_h   [MAXN * HID];
__device__ __align__(256) float g_t   [MAXN * HID];
__device__ __align__(256) float g_agg [MAXN * HID];
__device__ __align__(256) float g_gates[MAXN * 4 * HID];
__device__ __align__(256) float g_c   [MAXN * HID];
__device__ __align__(256) float g_ht  [MAXN * HID];
__device__ __align__(256) float g_peep[MAXN * 2 * HID];
__device__ __align__(256) float g_bnsums[2 * HID];
__device__ __align__(256) __half g_wt[4751360];      // transposed fp16 weights

// transposed-weight offsets (element counts)
#define WT_GCN0    0
#define WT_GCN1    32768
#define WT_GCN2    294912
#define WT_IH0     557056
#define WT_IH1     1605632
#define WT_HH1     2654208
#define WT_CH0_O   3702784
#define WT_CH1_FG  3964928
#define WT_CH1_O   4489216

// ---------------- fp16 tensor-core GEMM ----------------
// C[M,Nc] = A[M,K](fp32) @ Bt[Nc,K](fp16)^T.  128x128x32 block tile, 8 warps,
// 64x32 warp tile, mma.sync.m16n8k16.f16 with fp32 accum. Fragment-native smem:
// each (fragment, lane) is a contiguous uint4 (A) / uint2 (B). Double-buffered
// smem, ONE __syncthreads per K-chunk.

__device__ __forceinline__ uint32_t h2u(float2 v) {
    __half2 h = __floats2half2_rn(v.x, v.y);
    return *reinterpret_cast<uint32_t*>(&h);
}

template <int MODE>   // 0 = plain, 1 = +bias, 2 = += C
__global__ __launch_bounds__(256, 2)
void hgemm_kernel(const float* __restrict__ A, const __half* __restrict__ Bt,
                  float* __restrict__ C, const float* __restrict__ bias,
                  int M, int K, int ldc) {
    // A: 16 fragments (8 m-tiles x 2 k-tiles), 128 u32 each
    // B: 32 fragments (16 n-tiles x 2 k-tiles), 64 u32 each
    __shared__ uint32_t As[2][16 * 128];
    __shared__ uint32_t Bs[2][32 * 64];

    const int tid  = threadIdx.x;
    const int lane = tid & 31;
    const int warp = tid >> 5;
    const int bm = blockIdx.y * 128;
    const int bn = blockIdx.x * 128;
    const int wm = (warp >> 2) * 64;   // 0 or 64
    const int wn = (warp & 3) * 32;    // 0,32,64,96

    float acc[4][4][4];
#pragma unroll
    for (int i = 0; i < 4; i++)
#pragma unroll
        for (int j = 0; j < 4; j++)
#pragma unroll
            for (int k = 0; k < 4; k++) acc[i][j][k] = 0.f;

    uint32_t pa[2][4];   // prefetched A frag-lane pairs (half2-packed)
    uint32_t pb[4][2];   // prefetched B frag-lane pairs

    const int T = K >> 5;

    auto loadA = [&](int k0) {
#pragma unroll
        for (int it = 0; it < 2; it++) {
            int p  = tid + it * 256;
            int fi = p >> 5, ln = p & 31;
            int mt = fi >> 1, kt = fi & 1;
            int gq = ln >> 2, tg = ln & 3;
            int m  = bm + mt * 16 + gq;
            int c  = k0 + kt * 16 + tg * 2;
            const float* a0 = A + (size_t)m * K + c;
            bool ok0 = (m < M), ok1 = (m + 8 < M);
            float2 z = make_float2(0.f, 0.f);
            float2 v0 = ok0 ? *reinterpret_cast<const float2*>(a0) : z;
            float2 v1 = ok1 ? *reinterpret_cast<const float2*>(a0 + (size_t)8 * K) : z;
            float2 v2 = ok0 ? *reinterpret_cast<const float2*>(a0 + 8) : z;
            float2 v3 = ok1 ? *reinterpret_cast<const float2*>(a0 + (size_t)8 * K + 8) : z;
            pa[it][0] = h2u(v0); pa[it][1] = h2u(v1);
            pa[it][2] = h2u(v2); pa[it][3] = h2u(v3);
        }
    };
    auto loadB = [&](int k0) {
#pragma unroll
        for (int it = 0; it < 4; it++) {
            int p  = tid + it * 256;
            int fi = p >> 5, ln = p & 31;
            int nt = fi >> 1, kt = fi & 1;
            int gq = ln >> 2, tg = ln & 3;
            int n  = bn + nt * 8 + gq;
            int k  = k0 + kt * 16 + tg * 2;
            const __half* b0 = Bt + (size_t)n * K + k;
            pb[it][0] = *reinterpret_cast<const uint32_t*>(b0);
            pb[it][1] = *reinterpret_cast<const uint32_t*>(b0 + 8);
        }
    };
    auto store = [&](int buf) {
#pragma unroll
        for (int it = 0; it < 2; it++) {
            int p  = tid + it * 256;
            int fi = p >> 5, ln = p & 31;
            *reinterpret_cast<uint4*>(&As[buf][fi * 128 + ln * 4]) =
                make_uint4(pa[it][0], pa[it][1], pa[it][2], pa[it][3]);
        }
#pragma unroll
        for (int it = 0; it < 4; it++) {
            int p  = tid + it * 256;
            int fi = p >> 5, ln = p & 31;
            *reinterpret_cast<uint2*>(&Bs[buf][fi * 64 + ln * 2]) =
                make_uint2(pb[it][0], pb[it][1]);
        }
    };
    auto compute = [&](int buf) {
#pragma unroll
        for (int kt = 0; kt < 2; kt++) {
            uint32_t af[4][4];
#pragma unroll
            for (int mi = 0; mi < 4; mi++) {
                int fi = ((wm >> 4) + mi) * 2 + kt;
                uint4 v = *reinterpret_cast<const uint4*>(&As[buf][fi * 128 + lane * 4]);
                af[mi][0] = v.x; af[mi][1] = v.y; af[mi][2] = v.z; af[mi][3] = v.w;
            }
            uint32_t bf[4][2];
#pragma unroll
            for (int ni = 0; ni < 4; ni++) {
                int fi = ((wn >> 3) + ni) * 2 + kt;
                uint2 v = *reinterpret_cast<const uint2*>(&Bs[buf][fi * 64 + lane * 2]);
                bf[ni][0] = v.x; bf[ni][1] = v.y;
            }
#pragma unroll
            for (int mi = 0; mi < 4; mi++)
#pragma unroll
                for (int ni = 0; ni < 4; ni++) {
                    asm volatile(
                        "mma.sync.aligned.m16n8k16.row.col.f32.f16.f16.f32 "
                        "{%0,%1,%2,%3}, {%4,%5,%6,%7}, {%8,%9}, {%0,%1,%2,%3};\n"
                        : "+f"(acc[mi][ni][0]), "+f"(acc[mi][ni][1]),
                          "+f"(acc[mi][ni][2]), "+f"(acc[mi][ni][3])
                        : "r"(af[mi][0]), "r"(af[mi][1]), "r"(af[mi][2]), "r"(af[mi][3]),
                          "r"(bf[ni][0]), "r"(bf[ni][1]));
                }
        }
    };

    loadA(0); loadB(0);
    store(0);
    __syncthreads();
    for (int t = 0; t < T; t++) {
        const int buf = t & 1;
        if (t + 1 < T) { loadA((t + 1) << 5); loadB((t + 1) << 5); }
        compute(buf);
        if (t + 1 < T) store(buf ^ 1);
        __syncthreads();
    }

    // ---- epilogue ----
    const int gq = lane >> 2;
    const int rr = (lane & 3) << 1;
#pragma unroll
    for (int mi = 0; mi < 4; mi++) {
#pragma unroll
        for (int ni = 0; ni < 4; ni++) {
            int col = bn + wn + ni * 8 + rr;
#pragma unroll
            for (int h = 0; h < 2; h++) {
                int r = bm + wm + mi * 16 + gq + h * 8;
                if (r < M) {
                    float2 v = make_float2(acc[mi][ni][h * 2], acc[mi][ni][h * 2 + 1]);
                    if (MODE == 1) { v.x += bias[col]; v.y += bias[col + 1]; }
                    float* p = C + (size_t)r * ldc + col;
                    if (MODE == 2) {
                        float2 o = *reinterpret_cast<const float2*>(p);
                        v.x += o.x; v.y += o.y;
                    }
                    *reinterpret_cast<float2*>(p) = v;
                }
            }
        }
    }
}

// ---------------- weight transpose + fp16 convert: out[C,R] = half(in[R,C]^T) ----------------
__global__ void transpose_kernel(const float* __restrict__ in, int ldin,
                                 __half* __restrict__ out, int R, int C) {
    __shared__ float tile[32][33];
    int c0 = blockIdx.x * 32, r0 = blockIdx.y * 32;
    int tx = threadIdx.x, ty = threadIdx.y;
#pragma unroll
    for (int i = 0; i < 4; i++)
        tile[ty + 8 * i][tx] = in[(size_t)(r0 + ty + 8 * i) * ldin + c0 + tx];
    __syncthreads();
#pragma unroll
    for (int i = 0; i < 4; i++)
        out[(size_t)(c0 + ty + 8 * i) * R + r0 + tx] = __float2half(tile[tx][ty + 8 * i]);
}

// ---------------- utility kernels ----------------
__global__ void zero_kernel(float* __restrict__ p, long long n4) {
    long long i = (long long)blockIdx.x * blockDim.x + threadIdx.x;
    if (i < n4) reinterpret_cast<float4*>(p)[i] = make_float4(0.f, 0.f, 0.f, 0.f);
}

__global__ void agg_kernel(const float* __restrict__ feat,
                           const int* __restrict__ src,
                           const int* __restrict__ dst,
                           const float* __restrict__ ew,
                           float* __restrict__ out,
                           long long total, int shift, int C) {
    long long idx = (long long)blockIdx.x * blockDim.x + threadIdx.x;
    if (idx >= total) return;
    int e = (int)(idx >> shift);
    int g = ((int)idx & ((1 << shift) - 1)) << 2;
    float w = ew[e];
    int s = src[e], d = dst[e];
    float4 v = *reinterpret_cast<const float4*>(feat + (size_t)s * C + g);
    float* p = out + (size_t)d * C + g;
    atomicAdd(p + 0, v.x * w);
    atomicAdd(p + 1, v.y * w);
    atomicAdd(p + 2, v.z * w);
    atomicAdd(p + 3, v.w * w);
}

__global__ void bn_stats_kernel(const float* __restrict__ x, float* __restrict__ sums,
                                int Nrows, int C) {
    int col = threadIdx.x;
    int rowsPerBlock = (Nrows + gridDim.x - 1) / gridDim.x;
    int r0 = blockIdx.x * rowsPerBlock;
    int r1 = min(Nrows, r0 + rowsPerBlock);
    float s = 0.f, s2 = 0.f;
    for (int r = r0; r < r1; r++) {
        float v = x[(size_t)r * C + col];
        s += v;
        s2 = fmaf(v, v, s2);
    }
    atomicAdd(&sums[col], s);
    atomicAdd(&sums[C + col], s2);
}

__global__ void bn_apply_relu_kernel(const float* __restrict__ x, float* __restrict__ y,
                                     const float* __restrict__ sums,
                                     const float* __restrict__ gamma,
                                     const float* __restrict__ beta,
                                     long long total, float invN) {
    long long idx = (long long)blockIdx.x * blockDim.x + threadIdx.x;
    if (idx >= total) return;
    int col = (int)idx & (HID - 1);
    float mu  = sums[col] * invN;
    float var = sums[HID + col] * invN - mu * mu;
    float sc  = gamma[col] * rsqrtf(var + 1e-5f);
    float v   = (x[idx] - mu) * sc + beta[col];
    y[idx] = fmaxf(v, 0.f);
}

__device__ __forceinline__ float sigmoidf_(float x) { return 1.f / (1.f + expf(-x)); }

__global__ void cell0a_kernel(const float* __restrict__ gates, float* __restrict__ c,
                              long long total) {
    long long idx = (long long)blockIdx.x * blockDim.x + threadIdx.x;
    if (idx >= total) return;
    long long row = idx >> 9;
    int col = (int)idx & (HID - 1);
    const float* g = gates + row * (4 * HID);
    c[idx] = sigmoidf_(g[col]) * tanhf(g[2 * HID + col]);
}

__global__ void cell_ob_kernel(const float* __restrict__ gates, const float* __restrict__ op,
                               const float* __restrict__ c, float* __restrict__ ht,
                               long long total) {
    long long idx = (long long)blockIdx.x * blockDim.x + threadIdx.x;
    if (idx >= total) return;
    long long row = idx >> 9;
    int col = (int)idx & (HID - 1);
    float o = gates[row * (4 * HID) + 3 * HID + col] + op[idx];
    ht[idx] = sigmoidf_(o) * tanhf(c[idx]);
}

__global__ void cell1a_kernel(const float* __restrict__ gates, const float* __restrict__ cp,
                              float* __restrict__ c, long long total) {
    long long idx = (long long)blockIdx.x * blockDim.x + threadIdx.x;
    if (idx >= total) return;
    long long row = idx >> 9;
    int col = (int)idx & (HID - 1);
    const float* g = gates + row * (4 * HID);
    const float* p = cp + row * (2 * HID);
    float ig = sigmoidf_(g[col]);
    float fg = sigmoidf_(g[HID + col] + p[HID + col]);
    float gg = tanhf(g[2 * HID + col] + p[col]);
    c[idx] = fg * c[idx] + ig * gg;
}

__global__ __launch_bounds__(256)
void outproj_kernel(const float* __restrict__ A, const float* __restrict__ B,
                    float* __restrict__ C, const float* __restrict__ bias,
                    int M, int Ncols, int K) {
    long long idx = (long long)blockIdx.x * blockDim.x + threadIdx.x;
    long long total = (long long)M * Ncols;
    if (idx >= total) return;
    int row = (int)(idx / Ncols);
    int col = (int)(idx % Ncols);
    const float* a = A + (size_t)row * K;
    float s = bias[col];
    for (int k = 0; k < K; k += 4) {
        float4 v = *reinterpret_cast<const float4*>(a + k);
        s = fmaf(v.x, B[(size_t)(k + 0) * Ncols + col], s);
        s = fmaf(v.y, B[(size_t)(k + 1) * Ncols + col], s);
        s = fmaf(v.z, B[(size_t)(k + 2) * Ncols + col], s);
        s = fmaf(v.w, B[(size_t)(k + 3) * Ncols + col], s);
    }
    C[idx] = s;
}

// ---------------- host orchestration ----------------
static inline void run_hgemm(const float* A, const __half* Bt, float* C, const float* bias,
                             int M, int Nc, int K, int ldc, int mode) {
    dim3 grid(Nc / 128, (M + 127) / 128);
    if (mode == 1)
        hgemm_kernel<1><<<grid, 256>>>(A, Bt, C, bias, M, K, ldc);
    else if (mode == 2)
        hgemm_kernel<2><<<grid, 256>>>(A, Bt, C, bias, M, K, ldc);
    else
        hgemm_kernel<0><<<grid, 256>>>(A, Bt, C, bias, M, K, ldc);
}

static inline void run_transpose(const float* in, int ldin, __half* out, int R, int C) {
    dim3 grid(C / 32, R / 32);
    transpose_kernel<<<grid, dim3(32, 8)>>>(in, ldin, out, R, C);
}

static inline void run_zero(float* p, long long nfloats) {
    long long n4 = nfloats >> 2;
    int blocks = (int)((n4 + 255) / 256);
    zero_kernel<<<blocks, 256>>>(p, n4);
}

extern "C" void kernel_launch(void* const* d_in, const int* in_sizes, int n_in,
                              void* d_out, int out_size) {
    const float* x        = (const float*)d_in[0];
    const int*   ei       = (const int*)  d_in[1];   // [2,E]
    const float* ew       = (const float*)d_in[2];   // [E]
    const float* gcn0_W   = (const float*)d_in[3];   // [64,512]
    const float* gcn_W    = (const float*)d_in[5];   // [2,512,512]
    const float* bn_gamma = (const float*)d_in[7];   // [3,512]
    const float* bn_beta  = (const float*)d_in[8];   // [3,512]
    const float* w_ih     = (const float*)d_in[9];   // [2,512,2048]
    const float* w_hh     = (const float*)d_in[10];  // [2,512,2048]
    const float* w_ch     = (const float*)d_in[11];  // [2,512,1536]
    const float* lstm_b   = (const float*)d_in[12];  // [2,2048]
    const float* out_W    = (const float*)d_in[13];  // [512,12]
    const float* out_b    = (const float*)d_in[14];  // [12]
    float* out = (float*)d_out;

    const int N = in_sizes[0] / INCH;
    const int E = in_sizes[2];
    const int* src = ei;
    const int* dst = ei + E;
    const float invN = 1.f / (float)N;

    float *p_ax, *p_h, *p_t, *p_agg, *p_gates, *p_c, *p_ht, *p_peep, *p_sums;
    __half* p_wt;
    cudaGetSymbolAddress((void**)&p_ax,    g_ax);
    cudaGetSymbolAddress((void**)&p_h,     g_h);
    cudaGetSymbolAddress((void**)&p_t,     g_t);
    cudaGetSymbolAddress((void**)&p_agg,   g_agg);
    cudaGetSymbolAddress((void**)&p_gates, g_gates);
    cudaGetSymbolAddress((void**)&p_c,     g_c);
    cudaGetSymbolAddress((void**)&p_ht,    g_ht);
    cudaGetSymbolAddress((void**)&p_peep,  g_peep);
    cudaGetSymbolAddress((void**)&p_sums,  g_bnsums);
    cudaGetSymbolAddress((void**)&p_wt,    g_wt);

    const long long totNH = (long long)N * HID;
    const int blkNH = (int)((totNH + 255) / 256);
    const int bnStatBlocks = 160;

    // ---- transpose + fp16-convert all GEMM weights to [N,K] K-major ----
    run_transpose(gcn0_W, HID, p_wt + WT_GCN0, INCH, HID);
    run_transpose(gcn_W,             HID, p_wt + WT_GCN1, HID, HID);
    run_transpose(gcn_W + HID * HID, HID, p_wt + WT_GCN2, HID, HID);
    run_transpose(w_ih,                         4 * HID, p_wt + WT_IH0, HID, 4 * HID);
    run_transpose(w_ih + (size_t)HID * 4 * HID, 4 * HID, p_wt + WT_IH1, HID, 4 * HID);
    run_transpose(w_hh + (size_t)HID * 4 * HID, 4 * HID, p_wt + WT_HH1, HID, 4 * HID);
    run_transpose(w_ch + 2 * HID,               3 * HID, p_wt + WT_CH0_O, HID, HID);
    run_transpose(w_ch + (size_t)HID * 3 * HID,           3 * HID, p_wt + WT_CH1_FG, HID, 2 * HID);
    run_transpose(w_ch + (size_t)HID * 3 * HID + 2 * HID, 3 * HID, p_wt + WT_CH1_O,  HID, HID);

    // ---- GCN layer 0: aggregate input first (linearity), then matmul ----
    run_zero(p_ax, (long long)N * INCH);
    {
        long long total = (long long)E * (INCH / 4);
        agg_kernel<<<(int)((total + 255) / 256), 256>>>(x, src, dst, ew, p_ax, total, 4, INCH);
    }
    run_hgemm(p_ax, p_wt + WT_GCN0, p_t, nullptr, N, HID, INCH, HID, 0);
    run_zero(p_sums, 2 * HID);
    bn_stats_kernel<<<bnStatBlocks, HID>>>(p_t, p_sums, N, HID);
    bn_apply_relu_kernel<<<blkNH, 256>>>(p_t, p_h, p_sums, bn_gamma, bn_beta, totNH, invN);

    // ---- GCN layers 1..2 ----
    for (int l = 0; l < 2; l++) {
        run_hgemm(p_h, p_wt + (l == 0 ? WT_GCN1 : WT_GCN2), p_t, nullptr, N, HID, HID, HID, 0);
        run_zero(p_agg, totNH);
        long long total = (long long)E * (HID / 4);
        agg_kernel<<<(int)((total + 255) / 256), 256>>>(p_t, src, dst, ew, p_agg, total, 7, HID);
        run_zero(p_sums, 2 * HID);
        bn_stats_kernel<<<bnStatBlocks, HID>>>(p_agg, p_sums, N, HID);
        bn_apply_relu_kernel<<<blkNH, 256>>>(p_agg, p_h, p_sums,
                                             bn_gamma + (l + 1) * HID, bn_beta + (l + 1) * HID,
                                             totNH, invN);
    }

    // ---- LSTM layer 0 (h0 = c0 = 0: skip Whh and i/f peepholes) ----
    run_hgemm(p_h, p_wt + WT_IH0, p_gates, lstm_b, N, 4 * HID, HID, 4 * HID, 1);
    cell0a_kernel<<<blkNH, 256>>>(p_gates, p_c, totNH);
    run_hgemm(p_c, p_wt + WT_CH0_O, p_peep, nullptr, N, HID, HID, HID, 0);
    cell_ob_kernel<<<blkNH, 256>>>(p_gates, p_peep, p_c, p_ht, totNH);

    // ---- LSTM layer 1 (full) ----
    run_hgemm(p_h,  p_wt + WT_IH1, p_gates, lstm_b + 4 * HID, N, 4 * HID, HID, 4 * HID, 1);
    run_hgemm(p_ht, p_wt + WT_HH1, p_gates, nullptr,          N, 4 * HID, HID, 4 * HID, 2);
    run_hgemm(p_c,  p_wt + WT_CH1_FG, p_peep, nullptr, N, 2 * HID, HID, 2 * HID, 0);
    cell1a_kernel<<<blkNH, 256>>>(p_gates, p_peep, p_c, totNH);
    run_hgemm(p_c,  p_wt + WT_CH1_O, p_peep, nullptr, N, HID, HID, HID, 0);
    cell_ob_kernel<<<blkNH, 256>>>(p_gates, p_peep, p_c, p_ht, totNH);

    // ---- output projection (12-wide; FFMA path) ----
    {
        long long total = (long long)N * NPRED;
        outproj_kernel<<<(int)((total + 255) / 256), 256>>>(p_ht, out_W, out, out_b,
                                                            N, NPRED, HID);
    }
}

// round 5
// speedup vs baseline: 3.2348x; 1.4079x over previous
#include <cuda_runtime.h>
#include <cuda_fp16.h>
#include <math.h>
#include <stdint.h>

// ---------------- problem constants ----------------
#define MAXN   20000
#define MAXE   400000
#define INCH   64
#define HID    512
#define NPRED  12

// ---------------- scratch buffers (device globals; no runtime alloc) ----------------
__device__ __align__(256) float  g_t    [MAXN * HID];        // gemm out pre-agg
__device__ __align__(256) float  g_agg  [MAXN * HID];        // aggregated hidden (fp32)
__device__ __align__(256) float  g_gates[MAXN * 4 * HID];
__device__ __align__(256) float  g_c    [MAXN * HID];        // cell state fp32
__device__ __align__(256) float  g_ht   [MAXN * HID];        // hidden fp32 (for outproj)
__device__ __align__(256) float  g_peep [MAXN * 2 * HID];
__device__ __align__(256) float  g_bnsums[2 * HID];
__device__ __align__(256) __half g_axh  [MAXN * INCH];       // aggregated input fp16
__device__ __align__(256) __half g_hh   [MAXN * HID];        // activations fp16
__device__ __align__(256) __half g_ch   [MAXN * HID];        // cell state fp16
__device__ __align__(256) __half g_hth  [MAXN * HID];        // hidden fp16
__device__ __align__(256) __half g_wt   [4751360];           // transposed fp16 weights
// CSR
__device__ __align__(256) int    g_deg  [MAXN];
__device__ __align__(256) int    g_fill [MAXN];
__device__ __align__(256) int    g_rowptr[MAXN + 1];
__device__ __align__(256) int    g_esrc [MAXE];
__device__ __align__(256) float  g_ew2  [MAXE];

// transposed-weight offsets (element counts)
#define WT_GCN0    0
#define WT_GCN1    32768
#define WT_GCN2    294912
#define WT_IH0     557056
#define WT_IH1     1605632
#define WT_HH1     2654208
#define WT_CH0_O   3702784
#define WT_CH1_FG  3964928
#define WT_CH1_O   4489216

// ---------------- CSR build ----------------
__global__ void zero2_int_kernel(int* __restrict__ a, int* __restrict__ b, int n) {
    int i = blockIdx.x * blockDim.x + threadIdx.x;
    if (i < n) { a[i] = 0; b[i] = 0; }
}

__global__ void hist_kernel(const int* __restrict__ dst, int* __restrict__ deg, int E) {
    int e = blockIdx.x * blockDim.x + threadIdx.x;
    if (e < E) atomicAdd(&deg[dst[e]], 1);
}

__global__ void scan_kernel(const int* __restrict__ deg, int* __restrict__ rowptr, int n) {
    __shared__ int warp_sums[32];
    __shared__ int carry_s;
    int tid = threadIdx.x;             // 1024 threads
    int lane = tid & 31, wid = tid >> 5;
    if (tid == 0) { carry_s = 0; rowptr[0] = 0; }
    __syncthreads();
    for (int base = 0; base < n; base += 1024) {
        int i = base + tid;
        int v = (i < n) ? deg[i] : 0;
        int x = v;
#pragma unroll
        for (int o = 1; o < 32; o <<= 1) {
            int y = __shfl_up_sync(0xFFFFFFFFu, x, o);
            if (lane >= o) x += y;
        }
        if (lane == 31) warp_sums[wid] = x;
        __syncthreads();
        if (wid == 0) {
            int s = warp_sums[lane];
#pragma unroll
            for (int o = 1; o < 32; o <<= 1) {
                int y = __shfl_up_sync(0xFFFFFFFFu, s, o);
                if (lane >= o) s += y;
            }
            warp_sums[lane] = s;
        }
        __syncthreads();
        int incl = x + (wid > 0 ? warp_sums[wid - 1] : 0) + carry_s;
        if (i < n) rowptr[i + 1] = incl;
        __syncthreads();
        if (tid == 1023) carry_s = incl;
        __syncthreads();
    }
}

__global__ void fill_kernel(const int* __restrict__ src, const int* __restrict__ dst,
                            const float* __restrict__ ew,
                            const int* __restrict__ rowptr, int* __restrict__ fill,
                            int* __restrict__ esrc, float* __restrict__ ew2, int E) {
    int e = blockIdx.x * blockDim.x + threadIdx.x;
    if (e >= E) return;
    int d = dst[e];
    int pos = rowptr[d] + atomicAdd(&fill[d], 1);
    esrc[pos] = src[e];
    ew2[pos]  = ew[e];
}

// ---------------- CSR aggregation ----------------
// 512-wide: one block (128 thr) per node; thread owns 4 cols; fp32 out
__global__ __launch_bounds__(128)
void aggr512_kernel(const float* __restrict__ feat,
                    const int* __restrict__ rowptr, const int* __restrict__ esrc,
                    const float* __restrict__ ew2, float* __restrict__ out) {
    int node = blockIdx.x;
    int col = threadIdx.x * 4;
    int beg = rowptr[node], end = rowptr[node + 1];
    float4 acc = make_float4(0.f, 0.f, 0.f, 0.f);
    int j = beg;
    for (; j + 1 < end; j += 2) {
        int s0 = esrc[j], s1 = esrc[j + 1];
        float w0 = ew2[j], w1 = ew2[j + 1];
        float4 v0 = *reinterpret_cast<const float4*>(feat + (size_t)s0 * HID + col);
        float4 v1 = *reinterpret_cast<const float4*>(feat + (size_t)s1 * HID + col);
        acc.x = fmaf(w0, v0.x, acc.x); acc.y = fmaf(w0, v0.y, acc.y);
        acc.z = fmaf(w0, v0.z, acc.z); acc.w = fmaf(w0, v0.w, acc.w);
        acc.x = fmaf(w1, v1.x, acc.x); acc.y = fmaf(w1, v1.y, acc.y);
        acc.z = fmaf(w1, v1.z, acc.z); acc.w = fmaf(w1, v1.w, acc.w);
    }
    if (j < end) {
        int s0 = esrc[j];
        float w0 = ew2[j];
        float4 v0 = *reinterpret_cast<const float4*>(feat + (size_t)s0 * HID + col);
        acc.x = fmaf(w0, v0.x, acc.x); acc.y = fmaf(w0, v0.y, acc.y);
        acc.z = fmaf(w0, v0.z, acc.z); acc.w = fmaf(w0, v0.w, acc.w);
    }
    *reinterpret_cast<float4*>(out + (size_t)node * HID + col) = acc;
}

// 64-wide: block 128 thr = 8 nodes x 16 threads; fp16 out
__global__ __launch_bounds__(128)
void aggr64_kernel(const float* __restrict__ feat,
                   const int* __restrict__ rowptr, const int* __restrict__ esrc,
                   const float* __restrict__ ew2, __half* __restrict__ out, int N) {
    int node = blockIdx.x * 8 + (threadIdx.x >> 4);
    if (node >= N) return;
    int col = (threadIdx.x & 15) * 4;
    int beg = rowptr[node], end = rowptr[node + 1];
    float4 acc = make_float4(0.f, 0.f, 0.f, 0.f);
    for (int j = beg; j < end; j++) {
        int s = esrc[j];
        float w = ew2[j];
        float4 v = *reinterpret_cast<const float4*>(feat + (size_t)s * INCH + col);
        acc.x = fmaf(w, v.x, acc.x); acc.y = fmaf(w, v.y, acc.y);
        acc.z = fmaf(w, v.z, acc.z); acc.w = fmaf(w, v.w, acc.w);
    }
    __half2* o = reinterpret_cast<__half2*>(out + (size_t)node * INCH + col);
    o[0] = __floats2half2_rn(acc.x, acc.y);
    o[1] = __floats2half2_rn(acc.z, acc.w);
}

// ---------------- fp16 tensor-core GEMM ----------------
// C[M,Nc](fp32) = A[M,K](fp16) @ Bt[Nc,K](fp16)^T. 128x128x32 tile, 8 warps,
// m16n8k16 fp32-accum, fragment-native smem, double buffer, 1 barrier/chunk.
template <int MODE>   // 0 = plain, 1 = +bias, 2 = += C
__global__ __launch_bounds__(256, 2)
void hgemm_kernel(const __half* __restrict__ A, const __half* __restrict__ Bt,
                  float* __restrict__ C, const float* __restrict__ bias,
                  int M, int K, int ldc) {
    __shared__ uint32_t As[2][16 * 128];
    __shared__ uint32_t Bs[2][32 * 64];

    const int tid  = threadIdx.x;
    const int lane = tid & 31;
    const int warp = tid >> 5;
    const int bm = blockIdx.y * 128;
    const int bn = blockIdx.x * 128;
    const int wm = (warp >> 2) * 64;
    const int wn = (warp & 3) * 32;

    float acc[4][4][4];
#pragma unroll
    for (int i = 0; i < 4; i++)
#pragma unroll
        for (int j = 0; j < 4; j++)
#pragma unroll
            for (int k = 0; k < 4; k++) acc[i][j][k] = 0.f;

    uint32_t pa[2][4];
    uint32_t pb[4][2];
    const int T = K >> 5;

    auto loadA = [&](int k0) {
#pragma unroll
        for (int it = 0; it < 2; it++) {
            int p  = tid + it * 256;
            int fi = p >> 5, ln = p & 31;
            int mt = fi >> 1, kt = fi & 1;
            int gq = ln >> 2, tg = ln & 3;
            int m  = bm + mt * 16 + gq;
            int c  = k0 + kt * 16 + tg * 2;
            const __half* a0 = A + (size_t)m * K + c;
            bool ok0 = (m < M), ok1 = (m + 8 < M);
            pa[it][0] = ok0 ? *reinterpret_cast<const uint32_t*>(a0) : 0u;
            pa[it][1] = ok1 ? *reinterpret_cast<const uint32_t*>(a0 + (size_t)8 * K) : 0u;
            pa[it][2] = ok0 ? *reinterpret_cast<const uint32_t*>(a0 + 8) : 0u;
            pa[it][3] = ok1 ? *reinterpret_cast<const uint32_t*>(a0 + (size_t)8 * K + 8) : 0u;
        }
    };
    auto loadB = [&](int k0) {
#pragma unroll
        for (int it = 0; it < 4; it++) {
            int p  = tid + it * 256;
            int fi = p >> 5, ln = p & 31;
            int nt = fi >> 1, kt = fi & 1;
            int gq = ln >> 2, tg = ln & 3;
            int n  = bn + nt * 8 + gq;
            int k  = k0 + kt * 16 + tg * 2;
            const __half* b0 = Bt + (size_t)n * K + k;
            pb[it][0] = *reinterpret_cast<const uint32_t*>(b0);
            pb[it][1] = *reinterpret_cast<const uint32_t*>(b0 + 8);
        }
    };
    auto store = [&](int buf) {
#pragma unroll
        for (int it = 0; it < 2; it++) {
            int p  = tid + it * 256;
            int fi = p >> 5, ln = p & 31;
            *reinterpret_cast<uint4*>(&As[buf][fi * 128 + ln * 4]) =
                make_uint4(pa[it][0], pa[it][1], pa[it][2], pa[it][3]);
        }
#pragma unroll
        for (int it = 0; it < 4; it++) {
            int p  = tid + it * 256;
            int fi = p >> 5, ln = p & 31;
            *reinterpret_cast<uint2*>(&Bs[buf][fi * 64 + ln * 2]) =
                make_uint2(pb[it][0], pb[it][1]);
        }
    };
    auto compute = [&](int buf) {
#pragma unroll
        for (int kt = 0; kt < 2; kt++) {
            uint32_t af[4][4];
#pragma unroll
            for (int mi = 0; mi < 4; mi++) {
                int fi = ((wm >> 4) + mi) * 2 + kt;
                uint4 v = *reinterpret_cast<const uint4*>(&As[buf][fi * 128 + lane * 4]);
                af[mi][0] = v.x; af[mi][1] = v.y; af[mi][2] = v.z; af[mi][3] = v.w;
            }
            uint32_t bf[4][2];
#pragma unroll
            for (int ni = 0; ni < 4; ni++) {
                int fi = ((wn >> 3) + ni) * 2 + kt;
                uint2 v = *reinterpret_cast<const uint2*>(&Bs[buf][fi * 64 + lane * 2]);
                bf[ni][0] = v.x; bf[ni][1] = v.y;
            }
#pragma unroll
            for (int mi = 0; mi < 4; mi++)
#pragma unroll
                for (int ni = 0; ni < 4; ni++) {
                    asm volatile(
                        "mma.sync.aligned.m16n8k16.row.col.f32.f16.f16.f32 "
                        "{%0,%1,%2,%3}, {%4,%5,%6,%7}, {%8,%9}, {%0,%1,%2,%3};\n"
                        : "+f"(acc[mi][ni][0]), "+f"(acc[mi][ni][1]),
                          "+f"(acc[mi][ni][2]), "+f"(acc[mi][ni][3])
                        : "r"(af[mi][0]), "r"(af[mi][1]), "r"(af[mi][2]), "r"(af[mi][3]),
                          "r"(bf[ni][0]), "r"(bf[ni][1]));
                }
        }
    };

    loadA(0); loadB(0);
    store(0);
    __syncthreads();
    for (int t = 0; t < T; t++) {
        const int buf = t & 1;
        if (t + 1 < T) { loadA((t + 1) << 5); loadB((t + 1) << 5); }
        compute(buf);
        if (t + 1 < T) store(buf ^ 1);
        __syncthreads();
    }

    const int gq = lane >> 2;
    const int rr = (lane & 3) << 1;
#pragma unroll
    for (int mi = 0; mi < 4; mi++) {
#pragma unroll
        for (int ni = 0; ni < 4; ni++) {
            int col = bn + wn + ni * 8 + rr;
#pragma unroll
            for (int h = 0; h < 2; h++) {
                int r = bm + wm + mi * 16 + gq + h * 8;
                if (r < M) {
                    float2 v = make_float2(acc[mi][ni][h * 2], acc[mi][ni][h * 2 + 1]);
                    if (MODE == 1) { v.x += bias[col]; v.y += bias[col + 1]; }
                    float* p = C + (size_t)r * ldc + col;
                    if (MODE == 2) {
                        float2 o = *reinterpret_cast<const float2*>(p);
                        v.x += o.x; v.y += o.y;
                    }
                    *reinterpret_cast<float2*>(p) = v;
                }
            }
        }
    }
}

// ---------------- weight transpose + fp16 convert ----------------
__global__ void transpose_kernel(const float* __restrict__ in, int ldin,
                                 __half* __restrict__ out, int R, int C) {
    __shared__ float tile[32][33];
    int c0 = blockIdx.x * 32, r0 = blockIdx.y * 32;
    int tx = threadIdx.x, ty = threadIdx.y;
#pragma unroll
    for (int i = 0; i < 4; i++)
        tile[ty + 8 * i][tx] = in[(size_t)(r0 + ty + 8 * i) * ldin + c0 + tx];
    __syncthreads();
#pragma unroll
    for (int i = 0; i < 4; i++)
        out[(size_t)(c0 + ty + 8 * i) * R + r0 + tx] = __float2half(tile[tx][ty + 8 * i]);
}

// ---------------- BN / elementwise ----------------
__global__ void zero_kernel(float* __restrict__ p, long long n4) {
    long long i = (long long)blockIdx.x * blockDim.x + threadIdx.x;
    if (i < n4) reinterpret_cast<float4*>(p)[i] = make_float4(0.f, 0.f, 0.f, 0.f);
}

__global__ void bn_stats_kernel(const float* __restrict__ x, float* __restrict__ sums,
                                int Nrows, int C) {
    int col = threadIdx.x;
    int rowsPerBlock = (Nrows + gridDim.x - 1) / gridDim.x;
    int r0 = blockIdx.x * rowsPerBlock;
    int r1 = min(Nrows, r0 + rowsPerBlock);
    float s = 0.f, s2 = 0.f;
    for (int r = r0; r < r1; r++) {
        float v = x[(size_t)r * C + col];
        s += v;
        s2 = fmaf(v, v, s2);
    }
    atomicAdd(&sums[col], s);
    atomicAdd(&sums[C + col], s2);
}

// normalize + relu, write fp16 (GEMM-only consumer)
__global__ void bn_apply_relu_kernel(const float* __restrict__ x, __half2* __restrict__ y,
                                     const float* __restrict__ sums,
                                     const float* __restrict__ gamma,
                                     const float* __restrict__ beta,
                                     long long total2, float invN) {
    long long idx = (long long)blockIdx.x * blockDim.x + threadIdx.x;
    if (idx >= total2) return;
    int col = ((int)idx & 255) << 1;
    float2 xv = reinterpret_cast<const float2*>(x)[idx];
    float mu0  = sums[col] * invN,       mu1  = sums[col + 1] * invN;
    float var0 = sums[HID + col] * invN - mu0 * mu0;
    float var1 = sums[HID + col + 1] * invN - mu1 * mu1;
    float v0 = (xv.x - mu0) * (gamma[col] * rsqrtf(var0 + 1e-5f)) + beta[col];
    float v1 = (xv.y - mu1) * (gamma[col + 1] * rsqrtf(var1 + 1e-5f)) + beta[col + 1];
    y[idx] = __floats2half2_rn(fmaxf(v0, 0.f), fmaxf(v1, 0.f));
}

__device__ __forceinline__ float sigmoidf_(float x) { return 1.f / (1.f + expf(-x)); }

// layer0: c = sigmoid(i)*tanh(g); writes fp32 + fp16
__global__ void cell0a_kernel(const float* __restrict__ gates, float* __restrict__ c,
                              __half* __restrict__ ch, long long total) {
    long long idx = (long long)blockIdx.x * blockDim.x + threadIdx.x;
    if (idx >= total) return;
    long long row = idx >> 9;
    int col = (int)idx & (HID - 1);
    const float* g = gates + row * (4 * HID);
    float v = sigmoidf_(g[col]) * tanhf(g[2 * HID + col]);
    c[idx] = v;
    ch[idx] = __float2half(v);
}

// ht = sigmoid(o + opeep) * tanh(c); writes fp32 + fp16
__global__ void cell_ob_kernel(const float* __restrict__ gates, const float* __restrict__ op,
                               const float* __restrict__ c, float* __restrict__ ht,
                               __half* __restrict__ hth, long long total) {
    long long idx = (long long)blockIdx.x * blockDim.x + threadIdx.x;
    if (idx >= total) return;
    long long row = idx >> 9;
    int col = (int)idx & (HID - 1);
    float o = gates[row * (4 * HID) + 3 * HID + col] + op[idx];
    float v = sigmoidf_(o) * tanhf(c[idx]);
    ht[idx] = v;
    hth[idx] = __float2half(v);
}

// layer1: c <- f*c + i*g (peepholes); writes fp32 in place + fp16 copy
__global__ void cell1a_kernel(const float* __restrict__ gates, const float* __restrict__ cp,
                              float* __restrict__ c, __half* __restrict__ ch,
                              long long total) {
    long long idx = (long long)blockIdx.x * blockDim.x + threadIdx.x;
    if (idx >= total) return;
    long long row = idx >> 9;
    int col = (int)idx & (HID - 1);
    const float* g = gates + row * (4 * HID);
    const float* p = cp + row * (2 * HID);
    float ig = sigmoidf_(g[col]);
    float fg = sigmoidf_(g[HID + col] + p[HID + col]);
    float gg = tanhf(g[2 * HID + col] + p[col]);
    float v = fg * c[idx] + ig * gg;
    c[idx] = v;
    ch[idx] = __float2half(v);
}

__global__ __launch_bounds__(256)
void outproj_kernel(const float* __restrict__ A, const float* __restrict__ B,
                    float* __restrict__ C, const float* __restrict__ bias,
                    int M, int Ncols, int K) {
    long long idx = (long long)blockIdx.x * blockDim.x + threadIdx.x;
    long long total = (long long)M * Ncols;
    if (idx >= total) return;
    int row = (int)(idx / Ncols);
    int col = (int)(idx % Ncols);
    const float* a = A + (size_t)row * K;
    float s = bias[col];
    for (int k = 0; k < K; k += 4) {
        float4 v = *reinterpret_cast<const float4*>(a + k);
        s = fmaf(v.x, B[(size_t)(k + 0) * Ncols + col], s);
        s = fmaf(v.y, B[(size_t)(k + 1) * Ncols + col], s);
        s = fmaf(v.z, B[(size_t)(k + 2) * Ncols + col], s);
        s = fmaf(v.w, B[(size_t)(k + 3) * Ncols + col], s);
    }
    C[idx] = s;
}

// ---------------- host orchestration ----------------
static inline void run_hgemm(const __half* A, const __half* Bt, float* C, const float* bias,
                             int M, int Nc, int K, int ldc, int mode) {
    dim3 grid(Nc / 128, (M + 127) / 128);
    if (mode == 1)
        hgemm_kernel<1><<<grid, 256>>>(A, Bt, C, bias, M, K, ldc);
    else if (mode == 2)
        hgemm_kernel<2><<<grid, 256>>>(A, Bt, C, bias, M, K, ldc);
    else
        hgemm_kernel<0><<<grid, 256>>>(A, Bt, C, bias, M, K, ldc);
}

static inline void run_transpose(const float* in, int ldin, __half* out, int R, int C) {
    dim3 grid(C / 32, R / 32);
    transpose_kernel<<<grid, dim3(32, 8)>>>(in, ldin, out, R, C);
}

extern "C" void kernel_launch(void* const* d_in, const int* in_sizes, int n_in,
                              void* d_out, int out_size) {
    const float* x        = (const float*)d_in[0];
    const int*   ei       = (const int*)  d_in[1];
    const float* ew       = (const float*)d_in[2];
    const float* gcn0_W   = (const float*)d_in[3];
    const float* gcn_W    = (const float*)d_in[5];
    const float* bn_gamma = (const float*)d_in[7];
    const float* bn_beta  = (const float*)d_in[8];
    const float* w_ih     = (const float*)d_in[9];
    const float* w_hh     = (const float*)d_in[10];
    const float* w_ch     = (const float*)d_in[11];
    const float* lstm_b   = (const float*)d_in[12];
    const float* out_W    = (const float*)d_in[13];
    const float* out_b    = (const float*)d_in[14];
    float* out = (float*)d_out;

    const int N = in_sizes[0] / INCH;
    const int E = in_sizes[2];
    const int* src = ei;
    const int* dst = ei + E;
    const float invN = 1.f / (float)N;

    float *p_t, *p_agg, *p_gates, *p_c, *p_ht, *p_peep, *p_sums, *p_ew2;
    __half *p_wt, *p_axh, *p_hh, *p_ch, *p_hth;
    int *p_deg, *p_fill, *p_rowptr, *p_esrc;
    cudaGetSymbolAddress((void**)&p_t,     g_t);
    cudaGetSymbolAddress((void**)&p_agg,   g_agg);
    cudaGetSymbolAddress((void**)&p_gates, g_gates);
    cudaGetSymbolAddress((void**)&p_c,     g_c);
    cudaGetSymbolAddress((void**)&p_ht,    g_ht);
    cudaGetSymbolAddress((void**)&p_peep,  g_peep);
    cudaGetSymbolAddress((void**)&p_sums,  g_bnsums);
    cudaGetSymbolAddress((void**)&p_wt,    g_wt);
    cudaGetSymbolAddress((void**)&p_axh,   g_axh);
    cudaGetSymbolAddress((void**)&p_hh,    g_hh);
    cudaGetSymbolAddress((void**)&p_ch,    g_ch);
    cudaGetSymbolAddress((void**)&p_hth,   g_hth);
    cudaGetSymbolAddress((void**)&p_deg,   g_deg);
    cudaGetSymbolAddress((void**)&p_fill,  g_fill);
    cudaGetSymbolAddress((void**)&p_rowptr,g_rowptr);
    cudaGetSymbolAddress((void**)&p_esrc,  g_esrc);
    cudaGetSymbolAddress((void**)&p_ew2,   g_ew2);

    const long long totNH = (long long)N * HID;
    const int blkNH = (int)((totNH + 255) / 256);
    const int bnStatBlocks = 160;
    const int eBlocks = (E + 255) / 256;

    // ---- CSR build (by destination) ----
    zero2_int_kernel<<<(N + 255) / 256, 256>>>(p_deg, p_fill, N);
    hist_kernel<<<eBlocks, 256>>>(dst, p_deg, E);
    scan_kernel<<<1, 1024>>>(p_deg, p_rowptr, N);
    fill_kernel<<<eBlocks, 256>>>(src, dst, ew, p_rowptr, p_fill, p_esrc, p_ew2, E);

    // ---- transpose + fp16-convert weights ----
    run_transpose(gcn0_W, HID, p_wt + WT_GCN0, INCH, HID);
    run_transpose(gcn_W,             HID, p_wt + WT_GCN1, HID, HID);
    run_transpose(gcn_W + HID * HID, HID, p_wt + WT_GCN2, HID, HID);
    run_transpose(w_ih,                         4 * HID, p_wt + WT_IH0, HID, 4 * HID);
    run_transpose(w_ih + (size_t)HID * 4 * HID, 4 * HID, p_wt + WT_IH1, HID, 4 * HID);
    run_transpose(w_hh + (size_t)HID * 4 * HID, 4 * HID, p_wt + WT_HH1, HID, 4 * HID);
    run_transpose(w_ch + 2 * HID,               3 * HID, p_wt + WT_CH0_O, HID, HID);
    run_transpose(w_ch + (size_t)HID * 3 * HID,           3 * HID, p_wt + WT_CH1_FG, HID, 2 * HID);
    run_transpose(w_ch + (size_t)HID * 3 * HID + 2 * HID, 3 * HID, p_wt + WT_CH1_O,  HID, HID);

    // ---- GCN layer 0: aggregate input (CSR gather), then matmul ----
    aggr64_kernel<<<(N + 7) / 8, 128>>>(x, p_rowptr, p_esrc, p_ew2, p_axh, N);
    run_hgemm(p_axh, p_wt + WT_GCN0, p_t, nullptr, N, HID, INCH, HID, 0);
    zero_kernel<<<1, 256>>>(p_sums, 2 * HID / 4);
    bn_stats_kernel<<<bnStatBlocks, HID>>>(p_t, p_sums, N, HID);
    bn_apply_relu_kernel<<<(int)((totNH / 2 + 255) / 256), 256>>>(
        p_t, (__half2*)p_hh, p_sums, bn_gamma, bn_beta, totNH / 2, invN);

    // ---- GCN layers 1..2 ----
    for (int l = 0; l < 2; l++) {
        run_hgemm(p_hh, p_wt + (l == 0 ? WT_GCN1 : WT_GCN2), p_t, nullptr, N, HID, HID, HID, 0);
        aggr512_kernel<<<N, 128>>>(p_t, p_rowptr, p_esrc, p_ew2, p_agg);
        zero_kernel<<<1, 256>>>(p_sums, 2 * HID / 4);
        bn_stats_kernel<<<bnStatBlocks, HID>>>(p_agg, p_sums, N, HID);
        bn_apply_relu_kernel<<<(int)((totNH / 2 + 255) / 256), 256>>>(
            p_agg, (__half2*)p_hh, p_sums, bn_gamma + (l + 1) * HID, bn_beta + (l + 1) * HID,
            totNH / 2, invN);
    }

    // ---- LSTM layer 0 (h0 = c0 = 0) ----
    run_hgemm(p_hh, p_wt + WT_IH0, p_gates, lstm_b, N, 4 * HID, HID, 4 * HID, 1);
    cell0a_kernel<<<blkNH, 256>>>(p_gates, p_c, p_ch, totNH);
    run_hgemm(p_ch, p_wt + WT_CH0_O, p_peep, nullptr, N, HID, HID, HID, 0);
    cell_ob_kernel<<<blkNH, 256>>>(p_gates, p_peep, p_c, p_ht, p_hth, totNH);

    // ---- LSTM layer 1 ----
    run_hgemm(p_hh,  p_wt + WT_IH1, p_gates, lstm_b + 4 * HID, N, 4 * HID, HID, 4 * HID, 1);
    run_hgemm(p_hth, p_wt + WT_HH1, p_gates, nullptr,          N, 4 * HID, HID, 4 * HID, 2);
    run_hgemm(p_ch,  p_wt + WT_CH1_FG, p_peep, nullptr, N, 2 * HID, HID, 2 * HID, 0);
    cell1a_kernel<<<blkNH, 256>>>(p_gates, p_peep, p_c, p_ch, totNH);
    run_hgemm(p_ch,  p_wt + WT_CH1_O, p_peep, nullptr, N, HID, HID, HID, 0);
    cell_ob_kernel<<<blkNH, 256>>>(p_gates, p_peep, p_c, p_ht, p_hth, totNH);

    // ---- output projection ----
    {
        long long total = (long long)N * NPRED;
        outproj_kernel<<<(int)((total + 255) / 256), 256>>>(p_ht, out_W, out, out_b,
                                                            N, NPRED, HID);
    }
}

// round 6
// speedup vs baseline: 5.4296x; 1.6785x over previous
#include <cuda_runtime.h>
#include <cuda_fp16.h>
#include <math.h>
#include <stdint.h>

// ---------------- problem constants ----------------
#define MAXN   20000
#define MAXE   400000
#define INCH   64
#define HID    512
#define NPRED  12
#define MT_MAX 1256          // padded row-tiles: 20096 rows

// ---------------- scratch buffers (device globals; no runtime alloc) ----------------
__device__ __align__(256) float  g_t    [MAXN * HID];
__device__ __align__(256) float  g_agg  [MAXN * HID];
__device__ __align__(256) float  g_gates[MAXN * 4 * HID];
__device__ __align__(256) float  g_c    [MAXN * HID];
__device__ __align__(256) float  g_ht   [MAXN * HID];
__device__ __align__(256) float  g_peep [MAXN * 2 * HID];
__device__ __align__(256) float  g_bnsums[2 * HID];
// fragment-major fp16 A-operand buffers (padded to MT_MAX row-tiles; pad rows stay 0)
__device__ __align__(256) __half g_axh  [MT_MAX * 4  * 256];   // K=64
__device__ __align__(256) __half g_hh   [MT_MAX * 32 * 256];   // K=512
__device__ __align__(256) __half g_ch   [MT_MAX * 32 * 256];   // K=512
__device__ __align__(256) __half g_dual [MT_MAX * 64 * 256];   // K=1024: [h | ht]
// fragment-major fp16 weights
__device__ __align__(256) __half g_wt   [4751360];
// CSR
__device__ __align__(256) int    g_deg  [MAXN];
__device__ __align__(256) int    g_fill [MAXN];
__device__ __align__(256) int    g_rowptr[MAXN + 1];
__device__ __align__(256) int    g_esrc [MAXE];
__device__ __align__(256) float  g_ew2  [MAXE];

// weight offsets (halves)
#define WT_GCN0    0
#define WT_GCN1    32768
#define WT_GCN2    294912
#define WT_IH0     557056
#define WT_IHHH1   1605632
#define WT_CH0_O   3702784
#define WT_CH1_FG  3964928
#define WT_CH1_O   4489216

// ---------------- fragment-major addressing ----------------
// A-fragment (m16 x k16 tile): lane = (m&7)*4 + ((k>>1)&3); word = ((m>>3)&1) + 2*((k>>3)&1)
// offset (halves) of element (m, k even) ; Kt = K/16
__device__ __forceinline__ size_t afrag(int m, int k, int Kt) {
    int lane = ((m & 7) << 2) | ((k >> 1) & 3);
    int w = ((m >> 3) & 1) | (((k >> 3) & 1) << 1);
    return ((((size_t)(m >> 4) * Kt + (k >> 4)) << 5) + (size_t)lane) * 8 + (w << 1);
}

__device__ __forceinline__ uint32_t smem_u32(const void* p) {
    uint32_t a;
    asm("{ .reg .u64 t; cvta.to.shared.u64 t, %1; cvt.u32.u64 %0, t; }" : "=r"(a) : "l"(p));
    return a;
}

// ---------------- weight pack: W[K,N] row-major -> fragment-major Bt ----------------
__global__ void packB_kernel(const float* __restrict__ W, int ldw,
                             __half* __restrict__ out, int KtTot, int ktBase,
                             int K, int Nn) {
    int idx = blockIdx.x * blockDim.x + threadIdx.x;
    int total = (Nn >> 3) * (K >> 4) * 32;
    if (idx >= total) return;
    int lane = idx & 31;
    int f = idx >> 5;
    int KtS = K >> 4;
    int kt = f % KtS;
    int nt = f / KtS;
    int n = (nt << 3) + (lane >> 2);
    int k = (kt << 4) + ((lane & 3) << 1);
    const float* w0 = W + (size_t)k * ldw + n;
    __half2 lo = __floats2half2_rn(w0[0], w0[ldw]);
    __half2 hi = __floats2half2_rn(w0[(size_t)8 * ldw], w0[(size_t)9 * ldw]);
    size_t of = (((size_t)nt * KtTot + ktBase + kt) * 32 + lane) * 4;
    *reinterpret_cast<__half2*>(out + of)     = lo;
    *reinterpret_cast<__half2*>(out + of + 2) = hi;
}

// ---------------- CSR build ----------------
__global__ void zero2_int_kernel(int* __restrict__ a, int* __restrict__ b, int n) {
    int i = blockIdx.x * blockDim.x + threadIdx.x;
    if (i < n) { a[i] = 0; b[i] = 0; }
}

__global__ void hist_kernel(const int* __restrict__ dst, int* __restrict__ deg, int E) {
    int e = blockIdx.x * blockDim.x + threadIdx.x;
    if (e < E) atomicAdd(&deg[dst[e]], 1);
}

__global__ void scan_kernel(const int* __restrict__ deg, int* __restrict__ rowptr, int n) {
    __shared__ int warp_sums[32];
    __shared__ int carry_s;
    int tid = threadIdx.x;
    int lane = tid & 31, wid = tid >> 5;
    if (tid == 0) { carry_s = 0; rowptr[0] = 0; }
    __syncthreads();
    for (int base = 0; base < n; base += 1024) {
        int i = base + tid;
        int v = (i < n) ? deg[i] : 0;
        int x = v;
#pragma unroll
        for (int o = 1; o < 32; o <<= 1) {
            int y = __shfl_up_sync(0xFFFFFFFFu, x, o);
            if (lane >= o) x += y;
        }
        if (lane == 31) warp_sums[wid] = x;
        __syncthreads();
        if (wid == 0) {
            int s = warp_sums[lane];
#pragma unroll
            for (int o = 1; o < 32; o <<= 1) {
                int y = __shfl_up_sync(0xFFFFFFFFu, s, o);
                if (lane >= o) s += y;
            }
            warp_sums[lane] = s;
        }
        __syncthreads();
        int incl = x + (wid > 0 ? warp_sums[wid - 1] : 0) + carry_s;
        if (i < n) rowptr[i + 1] = incl;
        __syncthreads();
        if (tid == 1023) carry_s = incl;
        __syncthreads();
    }
}

__global__ void fill_kernel(const int* __restrict__ src, const int* __restrict__ dst,
                            const float* __restrict__ ew,
                            const int* __restrict__ rowptr, int* __restrict__ fill,
                            int* __restrict__ esrc, float* __restrict__ ew2, int E) {
    int e = blockIdx.x * blockDim.x + threadIdx.x;
    if (e >= E) return;
    int d = dst[e];
    int pos = rowptr[d] + atomicAdd(&fill[d], 1);
    esrc[pos] = src[e];
    ew2[pos]  = ew[e];
}

// ---------------- CSR aggregation ----------------
__global__ __launch_bounds__(128)
void aggr512_kernel(const float* __restrict__ feat,
                    const int* __restrict__ rowptr, const int* __restrict__ esrc,
                    const float* __restrict__ ew2, float* __restrict__ out) {
    int node = blockIdx.x;
    int col = threadIdx.x * 4;
    int beg = rowptr[node], end = rowptr[node + 1];
    float4 acc = make_float4(0.f, 0.f, 0.f, 0.f);
    int j = beg;
    for (; j + 1 < end; j += 2) {
        int s0 = esrc[j], s1 = esrc[j + 1];
        float w0 = ew2[j], w1 = ew2[j + 1];
        float4 v0 = *reinterpret_cast<const float4*>(feat + (size_t)s0 * HID + col);
        float4 v1 = *reinterpret_cast<const float4*>(feat + (size_t)s1 * HID + col);
        acc.x = fmaf(w0, v0.x, acc.x); acc.y = fmaf(w0, v0.y, acc.y);
        acc.z = fmaf(w0, v0.z, acc.z); acc.w = fmaf(w0, v0.w, acc.w);
        acc.x = fmaf(w1, v1.x, acc.x); acc.y = fmaf(w1, v1.y, acc.y);
        acc.z = fmaf(w1, v1.z, acc.z); acc.w = fmaf(w1, v1.w, acc.w);
    }
    if (j < end) {
        int s0 = esrc[j];
        float w0 = ew2[j];
        float4 v0 = *reinterpret_cast<const float4*>(feat + (size_t)s0 * HID + col);
        acc.x = fmaf(w0, v0.x, acc.x); acc.y = fmaf(w0, v0.y, acc.y);
        acc.z = fmaf(w0, v0.z, acc.z); acc.w = fmaf(w0, v0.w, acc.w);
    }
    *reinterpret_cast<float4*>(out + (size_t)node * HID + col) = acc;
}

// 64-wide aggregation, fp16 fragment-major out (Kt=4)
__global__ __launch_bounds__(128)
void aggr64_kernel(const float* __restrict__ feat,
                   const int* __restrict__ rowptr, const int* __restrict__ esrc,
                   const float* __restrict__ ew2, __half* __restrict__ out, int N) {
    int node = blockIdx.x * 8 + (threadIdx.x >> 4);
    if (node >= N) return;
    int col = (threadIdx.x & 15) * 4;
    int beg = rowptr[node], end = rowptr[node + 1];
    float4 acc = make_float4(0.f, 0.f, 0.f, 0.f);
    for (int j = beg; j < end; j++) {
        int s = esrc[j];
        float w = ew2[j];
        float4 v = *reinterpret_cast<const float4*>(feat + (size_t)s * INCH + col);
        acc.x = fmaf(w, v.x, acc.x); acc.y = fmaf(w, v.y, acc.y);
        acc.z = fmaf(w, v.z, acc.z); acc.w = fmaf(w, v.w, acc.w);
    }
    *reinterpret_cast<__half2*>(out + afrag(node, col,     4)) = __floats2half2_rn(acc.x, acc.y);
    *reinterpret_cast<__half2*>(out + afrag(node, col + 2, 4)) = __floats2half2_rn(acc.z, acc.w);
}

// ---------------- fp16 tensor-core GEMM, cp.async 3-stage ----------------
// C[M,Nc](fp32) = A(frag-major fp16) @ Bt(frag-major fp16)^T
#define CP_A16(dst, src) asm volatile("cp.async.cg.shared.global [%0], [%1], 16;" :: "r"(dst), "l"(src))
#define CP_B8(dst, src)  asm volatile("cp.async.ca.shared.global [%0], [%1], 8;"  :: "r"(dst), "l"(src))
#define CP_COMMIT()      asm volatile("cp.async.commit_group;" ::: "memory")
#define CP_WAIT1()       asm volatile("cp.async.wait_group 1;" ::: "memory")

template <int MODE>   // 0 = plain, 1 = +bias
__global__ __launch_bounds__(256, 2)
void hgemm_kernel(const __half* __restrict__ A, const __half* __restrict__ Bt,
                  float* __restrict__ C, const float* __restrict__ bias,
                  int M, int Kt, int ldc) {
    __shared__ uint32_t As[3][16 * 128];
    __shared__ uint32_t Bs[3][32 * 64];

    const int tid  = threadIdx.x;
    const int lane = tid & 31;
    const int warp = tid >> 5;
    const int bm = blockIdx.y * 128;
    const int bn = blockIdx.x * 128;
    const int wm = (warp >> 2) * 64;
    const int wn = (warp & 3) * 32;
    const int mtBase = bm >> 4;
    const int ntBase = bn >> 3;
    const int T = Kt >> 1;

    float acc[4][4][4];
#pragma unroll
    for (int i = 0; i < 4; i++)
#pragma unroll
        for (int j = 0; j < 4; j++)
#pragma unroll
            for (int k = 0; k < 4; k++) acc[i][j][k] = 0.f;

    auto issue = [&](int t, int stage) {
#pragma unroll
        for (int it = 0; it < 2; it++) {
            int p = tid + it * 256;
            int fi = p >> 5, ln = p & 31;
            const __half* src = A + ((((size_t)(mtBase + (fi >> 1)) * Kt) + (2 * t + (fi & 1))) * 32 + ln) * 8;
            CP_A16(smem_u32(&As[stage][fi * 128 + ln * 4]), src);
        }
#pragma unroll
        for (int it = 0; it < 4; it++) {
            int p = tid + it * 256;
            int fi = p >> 5, ln = p & 31;
            const __half* src = Bt + ((((size_t)(ntBase + (fi >> 1)) * Kt) + (2 * t + (fi & 1))) * 32 + ln) * 4;
            CP_B8(smem_u32(&Bs[stage][fi * 64 + ln * 2]), src);
        }
    };
    auto compute = [&](int buf) {
#pragma unroll
        for (int kt = 0; kt < 2; kt++) {
            uint32_t af[4][4];
#pragma unroll
            for (int mi = 0; mi < 4; mi++) {
                int fi = ((wm >> 4) + mi) * 2 + kt;
                uint4 v = *reinterpret_cast<const uint4*>(&As[buf][fi * 128 + lane * 4]);
                af[mi][0] = v.x; af[mi][1] = v.y; af[mi][2] = v.z; af[mi][3] = v.w;
            }
            uint32_t bf[4][2];
#pragma unroll
            for (int ni = 0; ni < 4; ni++) {
                int fi = ((wn >> 3) + ni) * 2 + kt;
                uint2 v = *reinterpret_cast<const uint2*>(&Bs[buf][fi * 64 + lane * 2]);
                bf[ni][0] = v.x; bf[ni][1] = v.y;
            }
#pragma unroll
            for (int mi = 0; mi < 4; mi++)
#pragma unroll
                for (int ni = 0; ni < 4; ni++) {
                    asm volatile(
                        "mma.sync.aligned.m16n8k16.row.col.f32.f16.f16.f32 "
                        "{%0,%1,%2,%3}, {%4,%5,%6,%7}, {%8,%9}, {%0,%1,%2,%3};\n"
                        : "+f"(acc[mi][ni][0]), "+f"(acc[mi][ni][1]),
                          "+f"(acc[mi][ni][2]), "+f"(acc[mi][ni][3])
                        : "r"(af[mi][0]), "r"(af[mi][1]), "r"(af[mi][2]), "r"(af[mi][3]),
                          "r"(bf[ni][0]), "r"(bf[ni][1]));
                }
        }
    };

    issue(0, 0);
    CP_COMMIT();
    if (T > 1) issue(1, 1);
    CP_COMMIT();
    for (int t = 0; t < T; t++) {
        CP_WAIT1();
        __syncthreads();
        if (t + 2 < T) issue(t + 2, (t + 2) % 3);
        CP_COMMIT();
        compute(t % 3);
    }

    const int gq = lane >> 2;
    const int rr = (lane & 3) << 1;
#pragma unroll
    for (int mi = 0; mi < 4; mi++) {
#pragma unroll
        for (int ni = 0; ni < 4; ni++) {
            int col = bn + wn + ni * 8 + rr;
#pragma unroll
            for (int h = 0; h < 2; h++) {
                int r = bm + wm + mi * 16 + gq + h * 8;
                if (r < M) {
                    float2 v = make_float2(acc[mi][ni][h * 2], acc[mi][ni][h * 2 + 1]);
                    if (MODE == 1) { v.x += bias[col]; v.y += bias[col + 1]; }
                    *reinterpret_cast<float2*>(C + (size_t)r * ldc + col) = v;
                }
            }
        }
    }
}

// ---------------- BN / elementwise ----------------
__global__ void zero_kernel(float* __restrict__ p, long long n4) {
    long long i = (long long)blockIdx.x * blockDim.x + threadIdx.x;
    if (i < n4) reinterpret_cast<float4*>(p)[i] = make_float4(0.f, 0.f, 0.f, 0.f);
}

__global__ void bn_stats_kernel(const float* __restrict__ x, float* __restrict__ sums,
                                int Nrows, int C) {
    int col = threadIdx.x;
    int rowsPerBlock = (Nrows + gridDim.x - 1) / gridDim.x;
    int r0 = blockIdx.x * rowsPerBlock;
    int r1 = min(Nrows, r0 + rowsPerBlock);
    float s = 0.f, s2 = 0.f;
    for (int r = r0; r < r1; r++) {
        float v = x[(size_t)r * C + col];
        s += v;
        s2 = fmaf(v, v, s2);
    }
    atomicAdd(&sums[col], s);
    atomicAdd(&sums[C + col], s2);
}

// normalize + relu; write frag-major fp16 into hh (Kt=32) and optionally dual (Kt=64, k-offset 0)
__global__ void bn_apply_relu_kernel(const float* __restrict__ x,
                                     __half* __restrict__ hh, __half* __restrict__ dual,
                                     const float* __restrict__ sums,
                                     const float* __restrict__ gamma,
                                     const float* __restrict__ beta,
                                     int N, float invN) {
    int idx = blockIdx.x * blockDim.x + threadIdx.x;
    if (idx >= N * 256) return;
    int row = idx >> 8;
    int col = (idx & 255) << 1;
    float2 xv = reinterpret_cast<const float2*>(x)[idx];
    float mu0  = sums[col] * invN,  mu1 = sums[col + 1] * invN;
    float var0 = sums[HID + col] * invN - mu0 * mu0;
    float var1 = sums[HID + col + 1] * invN - mu1 * mu1;
    float v0 = (xv.x - mu0) * (gamma[col] * rsqrtf(var0 + 1e-5f)) + beta[col];
    float v1 = (xv.y - mu1) * (gamma[col + 1] * rsqrtf(var1 + 1e-5f)) + beta[col + 1];
    __half2 h = __floats2half2_rn(fmaxf(v0, 0.f), fmaxf(v1, 0.f));
    *reinterpret_cast<__half2*>(hh + afrag(row, col, 32)) = h;
    if (dual) *reinterpret_cast<__half2*>(dual + afrag(row, col, 64)) = h;
}

__device__ __forceinline__ float sigmoidf_(float x) { return 1.f / (1.f + expf(-x)); }

// layer0: c = sigmoid(i)*tanh(g); write c fp32 + ch frag-major fp16
__global__ void cell0a_kernel(const float* __restrict__ gates, float* __restrict__ c,
                              __half* __restrict__ ch, int N) {
    int idx = blockIdx.x * blockDim.x + threadIdx.x;
    if (idx >= N * 256) return;
    int row = idx >> 8;
    int col = (idx & 255) << 1;
    const float* g = gates + (size_t)row * 2048;
    float2 iv = *reinterpret_cast<const float2*>(g + col);
    float2 gv = *reinterpret_cast<const float2*>(g + 1024 + col);
    float v0 = sigmoidf_(iv.x) * tanhf(gv.x);
    float v1 = sigmoidf_(iv.y) * tanhf(gv.y);
    *reinterpret_cast<float2*>(c + (size_t)row * HID + col) = make_float2(v0, v1);
    *reinterpret_cast<__half2*>(ch + afrag(row, col, 32)) = __floats2half2_rn(v0, v1);
}

// ht = sigmoid(o + opeep) * tanh(c)
// L=0: write fp16 into dual at k-offset 512 (Kt=64). L=1: write fp32 ht.
template <int L>
__global__ void cell_ob_kernel(const float* __restrict__ gates, const float* __restrict__ op,
                               const float* __restrict__ c,
                               float* __restrict__ ht, __half* __restrict__ dual, int N) {
    int idx = blockIdx.x * blockDim.x + threadIdx.x;
    if (idx >= N * 256) return;
    int row = idx >> 8;
    int col = (idx & 255) << 1;
    float2 ov = *reinterpret_cast<const float2*>(gates + (size_t)row * 2048 + 1536 + col);
    float2 pv = *reinterpret_cast<const float2*>(op + (size_t)row * HID + col);
    float2 cv = *reinterpret_cast<const float2*>(c + (size_t)row * HID + col);
    float v0 = sigmoidf_(ov.x + pv.x) * tanhf(cv.x);
    float v1 = sigmoidf_(ov.y + pv.y) * tanhf(cv.y);
    if (L == 0)
        *reinterpret_cast<__half2*>(dual + afrag(row, 512 + col, 64)) = __floats2half2_rn(v0, v1);
    else
        *reinterpret_cast<float2*>(ht + (size_t)row * HID + col) = make_float2(v0, v1);
}

// layer1: c <- f*c + i*g (with peepholes); write c fp32 + ch fp16
__global__ void cell1a_kernel(const float* __restrict__ gates, const float* __restrict__ cp,
                              float* __restrict__ c, __half* __restrict__ ch, int N) {
    int idx = blockIdx.x * blockDim.x + threadIdx.x;
    if (idx >= N * 256) return;
    int row = idx >> 8;
    int col = (idx & 255) << 1;
    const float* g = gates + (size_t)row * 2048;
    float2 iv = *reinterpret_cast<const float2*>(g + col);
    float2 fv = *reinterpret_cast<const float2*>(g + 512 + col);
    float2 gv = *reinterpret_cast<const float2*>(g + 1024 + col);
    float2 pg = *reinterpret_cast<const float2*>(cp + (size_t)row * 1024 + col);
    float2 pf = *reinterpret_cast<const float2*>(cp + (size_t)row * 1024 + 512 + col);
    float2 cv = *reinterpret_cast<const float2*>(c + (size_t)row * HID + col);
    float v0 = sigmoidf_(fv.x + pf.x) * cv.x + sigmoidf_(iv.x) * tanhf(gv.x + pg.x);
    float v1 = sigmoidf_(fv.y + pf.y) * cv.y + sigmoidf_(iv.y) * tanhf(gv.y + pg.y);
    *reinterpret_cast<float2*>(c + (size_t)row * HID + col) = make_float2(v0, v1);
    *reinterpret_cast<__half2*>(ch + afrag(row, col, 32)) = __floats2half2_rn(v0, v1);
}

__global__ __launch_bounds__(256)
void outproj_kernel(const float* __restrict__ A, const float* __restrict__ B,
                    float* __restrict__ C, const float* __restrict__ bias,
                    int M, int Ncols, int K) {
    long long idx = (long long)blockIdx.x * blockDim.x + threadIdx.x;
    long long total = (long long)M * Ncols;
    if (idx >= total) return;
    int row = (int)(idx / Ncols);
    int col = (int)(idx % Ncols);
    const float* a = A + (size_t)row * K;
    float s = bias[col];
    for (int k = 0; k < K; k += 4) {
        float4 v = *reinterpret_cast<const float4*>(a + k);
        s = fmaf(v.x, B[(size_t)(k + 0) * Ncols + col], s);
        s = fmaf(v.y, B[(size_t)(k + 1) * Ncols + col], s);
        s = fmaf(v.z, B[(size_t)(k + 2) * Ncols + col], s);
        s = fmaf(v.w, B[(size_t)(k + 3) * Ncols + col], s);
    }
    C[idx] = s;
}

// ---------------- host orchestration ----------------
static inline void run_hgemm(const __half* A, const __half* Bt, float* C, const float* bias,
                             int M, int Nc, int Kt, int ldc, int mode) {
    dim3 grid(Nc / 128, (M + 127) / 128);
    if (mode == 1)
        hgemm_kernel<1><<<grid, 256>>>(A, Bt, C, bias, M, Kt, ldc);
    else
        hgemm_kernel<0><<<grid, 256>>>(A, Bt, C, bias, M, Kt, ldc);
}

static inline void run_pack(const float* W, int ldw, __half* out, int KtTot, int ktBase,
                            int K, int Nn) {
    int total = (Nn / 8) * (K / 16) * 32;
    packB_kernel<<<(total + 255) / 256, 256>>>(W, ldw, out, KtTot, ktBase, K, Nn);
}

extern "C" void kernel_launch(void* const* d_in, const int* in_sizes, int n_in,
                              void* d_out, int out_size) {
    const float* x        = (const float*)d_in[0];
    const int*   ei       = (const int*)  d_in[1];
    const float* ew       = (const float*)d_in[2];
    const float* gcn0_W   = (const float*)d_in[3];
    const float* gcn_W    = (const float*)d_in[5];
    const float* bn_gamma = (const float*)d_in[7];
    const float* bn_beta  = (const float*)d_in[8];
    const float* w_ih     = (const float*)d_in[9];
    const float* w_hh     = (const float*)d_in[10];
    const float* w_ch     = (const float*)d_in[11];
    const float* lstm_b   = (const float*)d_in[12];
    const float* out_W    = (const float*)d_in[13];
    const float* out_b    = (const float*)d_in[14];
    float* out = (float*)d_out;

    const int N = in_sizes[0] / INCH;
    const int E = in_sizes[2];
    const int* src = ei;
    const int* dst = ei + E;
    const float invN = 1.f / (float)N;

    float *p_t, *p_agg, *p_gates, *p_c, *p_ht, *p_peep, *p_sums, *p_ew2;
    __half *p_wt, *p_axh, *p_hh, *p_ch, *p_dual;
    int *p_deg, *p_fill, *p_rowptr, *p_esrc;
    cudaGetSymbolAddress((void**)&p_t,     g_t);
    cudaGetSymbolAddress((void**)&p_agg,   g_agg);
    cudaGetSymbolAddress((void**)&p_gates, g_gates);
    cudaGetSymbolAddress((void**)&p_c,     g_c);
    cudaGetSymbolAddress((void**)&p_ht,    g_ht);
    cudaGetSymbolAddress((void**)&p_peep,  g_peep);
    cudaGetSymbolAddress((void**)&p_sums,  g_bnsums);
    cudaGetSymbolAddress((void**)&p_wt,    g_wt);
    cudaGetSymbolAddress((void**)&p_axh,   g_axh);
    cudaGetSymbolAddress((void**)&p_hh,    g_hh);
    cudaGetSymbolAddress((void**)&p_ch,    g_ch);
    cudaGetSymbolAddress((void**)&p_dual,  g_dual);
    cudaGetSymbolAddress((void**)&p_deg,   g_deg);
    cudaGetSymbolAddress((void**)&p_fill,  g_fill);
    cudaGetSymbolAddress((void**)&p_rowptr,g_rowptr);
    cudaGetSymbolAddress((void**)&p_esrc,  g_esrc);
    cudaGetSymbolAddress((void**)&p_ew2,   g_ew2);

    const int blkNH2 = (N * 256 + 255) / 256;
    const int bnStatBlocks = 160;
    const int eBlocks = (E + 255) / 256;

    // ---- CSR build ----
    zero2_int_kernel<<<(N + 255) / 256, 256>>>(p_deg, p_fill, N);
    hist_kernel<<<eBlocks, 256>>>(dst, p_deg, E);
    scan_kernel<<<1, 1024>>>(p_deg, p_rowptr, N);
    fill_kernel<<<eBlocks, 256>>>(src, dst, ew, p_rowptr, p_fill, p_esrc, p_ew2, E);

    // ---- pack weights to fragment-major fp16 ----
    run_pack(gcn0_W, HID, p_wt + WT_GCN0, 4, 0, INCH, HID);
    run_pack(gcn_W,             HID, p_wt + WT_GCN1, 32, 0, HID, HID);
    run_pack(gcn_W + HID * HID, HID, p_wt + WT_GCN2, 32, 0, HID, HID);
    run_pack(w_ih, 4 * HID, p_wt + WT_IH0, 32, 0, HID, 4 * HID);
    run_pack(w_ih + (size_t)HID * 4 * HID, 4 * HID, p_wt + WT_IHHH1, 64, 0,  HID, 4 * HID);
    run_pack(w_hh + (size_t)HID * 4 * HID, 4 * HID, p_wt + WT_IHHH1, 64, 32, HID, 4 * HID);
    run_pack(w_ch + 2 * HID, 3 * HID, p_wt + WT_CH0_O, 32, 0, HID, HID);
    run_pack(w_ch + (size_t)HID * 3 * HID,            3 * HID, p_wt + WT_CH1_FG, 32, 0, HID, 2 * HID);
    run_pack(w_ch + (size_t)HID * 3 * HID + 2 * HID,  3 * HID, p_wt + WT_CH1_O,  32, 0, HID, HID);

    // ---- GCN layer 0 ----
    aggr64_kernel<<<(N + 7) / 8, 128>>>(x, p_rowptr, p_esrc, p_ew2, p_axh, N);
    run_hgemm(p_axh, p_wt + WT_GCN0, p_t, nullptr, N, HID, 4, HID, 0);
    zero_kernel<<<1, 256>>>(p_sums, 2 * HID / 4);
    bn_stats_kernel<<<bnStatBlocks, HID>>>(p_t, p_sums, N, HID);
    bn_apply_relu_kernel<<<blkNH2, 256>>>(p_t, p_hh, nullptr, p_sums,
                                          bn_gamma, bn_beta, N, invN);

    // ---- GCN layers 1..2 ----
    for (int l = 0; l < 2; l++) {
        run_hgemm(p_hh, p_wt + (l == 0 ? WT_GCN1 : WT_GCN2), p_t, nullptr, N, HID, 32, HID, 0);
        aggr512_kernel<<<N, 128>>>(p_t, p_rowptr, p_esrc, p_ew2, p_agg);
        zero_kernel<<<1, 256>>>(p_sums, 2 * HID / 4);
        bn_stats_kernel<<<bnStatBlocks, HID>>>(p_agg, p_sums, N, HID);
        bn_apply_relu_kernel<<<blkNH2, 256>>>(p_agg, p_hh, (l == 1) ? p_dual : nullptr,
                                              p_sums, bn_gamma + (l + 1) * HID,
                                              bn_beta + (l + 1) * HID, N, invN);
    }

    // ---- LSTM layer 0 (h0 = c0 = 0) ----
    run_hgemm(p_hh, p_wt + WT_IH0, p_gates, lstm_b, N, 4 * HID, 32, 4 * HID, 1);
    cell0a_kernel<<<blkNH2, 256>>>(p_gates, p_c, p_ch, N);
    run_hgemm(p_ch, p_wt + WT_CH0_O, p_peep, nullptr, N, HID, 32, HID, 0);
    cell_ob_kernel<0><<<blkNH2, 256>>>(p_gates, p_peep, p_c, nullptr, p_dual, N);

    // ---- LSTM layer 1 (fused [h|ht] @ [Wih1;Whh1], K=1024) ----
    run_hgemm(p_dual, p_wt + WT_IHHH1, p_gates, lstm_b + 4 * HID, N, 4 * HID, 64, 4 * HID, 1);
    run_hgemm(p_ch,   p_wt + WT_CH1_FG, p_peep, nullptr, N, 2 * HID, 32, 2 * HID, 0);
    cell1a_kernel<<<blkNH2, 256>>>(p_gates, p_peep, p_c, p_ch, N);
    run_hgemm(p_ch,   p_wt + WT_CH1_O, p_peep, nullptr, N, HID, 32, HID, 0);
    cell_ob_kernel<1><<<blkNH2, 256>>>(p_gates, p_peep, p_c, p_ht, nullptr, N);

    // ---- output projection ----
    {
        long long total = (long long)N * NPRED;
        outproj_kernel<<<(int)((total + 255) / 256), 256>>>(p_ht, out_W, out, out_b,
                                                            N, NPRED, HID);
    }
}